// round 15
// baseline (speedup 1.0000x reference)
#include <cuda_runtime.h>
#include <cuda_bf16.h>

#define NMAX 100000
#define EMAX 1600000

// ---------------- scratch ----------------
static __device__ __align__(16) unsigned g_hoh[ (size_t)NMAX*64 ];   // h_o bf16 hi (k-pair packed)
static __device__ __align__(16) unsigned g_hol[ (size_t)NMAX*64 ];
static __device__ __align__(16) unsigned g_hsh[ (size_t)NMAX*64 ];
static __device__ __align__(16) unsigned g_hsl[ (size_t)NMAX*64 ];
static __device__ __align__(16) short  g_q1o [ (size_t)NMAX*128 ];
static __device__ __align__(16) short  g_q1s [ (size_t)NMAX*128 ];
static __device__ __align__(16) float  g_s1o [ NMAX ];
static __device__ __align__(16) float  g_s1s [ NMAX ];
static __device__ __align__(16) float4 g_tO  [ NMAX ];
static __device__ __align__(16) float4 g_tS  [ NMAX ];
static __device__ __align__(16) float4 g_aggO[ NMAX ];
static __device__ __align__(16) float4 g_aggS[ NMAX ];
static __device__ __align__(16) float  g_av  [ NMAX ];
static __device__ __align__(16) float  g_bv  [ NMAX ];
static __device__ __align__(16) float  g_wc  [ 144 ];   // w[0..127], c@128, dots@129..134
static __device__ __align__(16) int    g_rp  [ 2*(NMAX+1) ];
static __device__ __align__(16) int2   g_ep  [ (size_t)2*EMAX ];
static __device__ __align__(16) int    g_cur [ 2*NMAX ];
static __device__ __align__(16) int    g_bsum[ 256 ];
static __device__ __align__(16) unsigned g_Wh1o[64*128], g_Wl1o[64*128];
static __device__ __align__(16) unsigned g_Wh1s[64*128], g_Wl1s[64*128];
static __device__ __align__(16) unsigned g_Wh2o[64*64],  g_Wl2o[64*64];
static __device__ __align__(16) unsigned g_Wh2s[64*64],  g_Wl2s[64*64];
static __device__            int   g_i64flag;

// ---------------- stream/event resources (static init) ----------------
struct StreamRes {
    cudaStream_t sB;
    cudaEvent_t evFork, evG1;
    bool ok;
    StreamRes() : sB(0), evFork(0), evG1(0), ok(false) {
        if (cudaStreamCreate(&sB) != cudaSuccess) { sB = 0; return; }
        if (cudaEventCreateWithFlags(&evFork, cudaEventDisableTiming) != cudaSuccess) return;
        if (cudaEventCreateWithFlags(&evG1,   cudaEventDisableTiming) != cudaSuccess) return;
        ok = true;
    }
};
static StreamRes g_sr;

// ---------------- bf16 hi/lo split ----------------
__device__ __forceinline__ void bsplit2(float x0, float x1, unsigned& h, unsigned& l) {
    unsigned hp;
    asm("cvt.rn.bf16x2.f32 %0, %1, %2;" : "=r"(hp) : "f"(x1), "f"(x0));
    float fh0 = __uint_as_float(hp << 16);
    float fh1 = __uint_as_float(hp & 0xFFFF0000u);
    float r0 = x0 - fh0, r1 = x1 - fh1;
    asm("cvt.rn.bf16x2.f32 %0, %1, %2;" : "=r"(l) : "f"(r1), "f"(r0));
    h = hp;
}

#define MMA_BF16(acc, a, b0, b1)                                              \
    asm volatile(                                                             \
        "mma.sync.aligned.m16n8k16.row.col.f32.bf16.bf16.f32 "                \
        "{%0,%1,%2,%3}, {%4,%5,%6,%7}, {%8,%9}, {%0,%1,%2,%3};\n"             \
        : "+f"(acc[0]), "+f"(acc[1]), "+f"(acc[2]), "+f"(acc[3])              \
        : "r"(a[0]), "r"(a[1]), "r"(a[2]), "r"(a[3]), "r"(b0), "r"(b1))

// ---------------- GEMM-128 (fp32 A, in-kernel split) + int16 rowquant ----------------
__global__ __launch_bounds__(256, 2)
void k_gemm_q128(const float* __restrict__ A,
                 const unsigned* __restrict__ Bh, const unsigned* __restrict__ Bl,
                 short* __restrict__ q, float* __restrict__ sc, int M) {
    constexpr int BM = 128, BK = 16, KTOT = 128, NCH = KTOT / BK, NST = 3;
    constexpr int BN = 128, WN = 64, NT = 8;
    constexpr int SAW = BK + 4, SBW = BN + 8;
    extern __shared__ char dynsmem[];
    float*    sA   = (float*)dynsmem;
    unsigned* sBh  = (unsigned*)(dynsmem + NST * BM * SAW * 4);
    unsigned* sBl  = sBh + NST * 8 * SBW;
    int*      rmax = (int*)(sBl + NST * 8 * SBW);

    const int tid  = threadIdx.x;
    const int wid  = tid >> 5, lane = tid & 31;
    const int wm   = wid & 3,  wn   = wid >> 2;
    const int g    = lane >> 2, tig = lane & 3;
    const int row0 = blockIdx.x * BM;

    if (tid < BM) rmax[tid] = 0;

    float acc[2][NT][4];
#pragma unroll
    for (int mt = 0; mt < 2; ++mt)
#pragma unroll
        for (int nt = 0; nt < NT; ++nt)
#pragma unroll
            for (int i = 0; i < 4; ++i) acc[mt][nt][i] = 0.f;

    auto loadA = [&](int ck, int st) {
#pragma unroll
        for (int i = 0; i < 2; ++i) {
            int idx = i * 256 + tid;
            int r = idx >> 2, c4 = idx & 3;
            const float* gp = A + (size_t)(row0 + r) * KTOT + ck * BK + c4 * 4;
            unsigned sp = (unsigned)__cvta_generic_to_shared(&sA[(st * BM + r) * SAW + c4 * 4]);
            int bytes = (row0 + r < M) ? 16 : 0;
            asm volatile("cp.async.cg.shared.global [%0], [%1], 16, %2;\n"
                         :: "r"(sp), "l"(gp), "r"(bytes));
        }
    };
    auto loadB = [&](int ck, int st) {
        int r = tid >> 5, c4 = tid & 31;
        const unsigned* gh = Bh + (size_t)(ck * 8 + r) * BN + c4 * 4;
        const unsigned* gl = Bl + (size_t)(ck * 8 + r) * BN + c4 * 4;
        unsigned sph = (unsigned)__cvta_generic_to_shared(&sBh[(st * 8 + r) * SBW + c4 * 4]);
        unsigned spl = (unsigned)__cvta_generic_to_shared(&sBl[(st * 8 + r) * SBW + c4 * 4]);
        asm volatile("cp.async.cg.shared.global [%0], [%1], 16, 16;\n" :: "r"(sph), "l"(gh));
        asm volatile("cp.async.cg.shared.global [%0], [%1], 16, 16;\n" :: "r"(spl), "l"(gl));
    };
    auto compute = [&](int st) {
        unsigned ah[2][4], al[2][4];
#pragma unroll
        for (int mt = 0; mt < 2; ++mt) {
            int r = wm * 32 + mt * 16 + g;
            float2 p0 = *(const float2*)&sA[(st * BM + r    ) * SAW + 2 * tig];
            float2 p1 = *(const float2*)&sA[(st * BM + r + 8) * SAW + 2 * tig];
            float2 p2 = *(const float2*)&sA[(st * BM + r    ) * SAW + 2 * tig + 8];
            float2 p3 = *(const float2*)&sA[(st * BM + r + 8) * SAW + 2 * tig + 8];
            bsplit2(p0.x, p0.y, ah[mt][0], al[mt][0]);
            bsplit2(p1.x, p1.y, ah[mt][1], al[mt][1]);
            bsplit2(p2.x, p2.y, ah[mt][2], al[mt][2]);
            bsplit2(p3.x, p3.y, ah[mt][3], al[mt][3]);
        }
#pragma unroll
        for (int nt = 0; nt < NT; ++nt) {
            int c = wn * WN + nt * 8 + g;
            unsigned b0h = sBh[(st * 8 + tig    ) * SBW + c];
            unsigned b1h = sBh[(st * 8 + tig + 4) * SBW + c];
            unsigned b0l = sBl[(st * 8 + tig    ) * SBW + c];
            unsigned b1l = sBl[(st * 8 + tig + 4) * SBW + c];
#pragma unroll
            for (int mt = 0; mt < 2; ++mt) {
                MMA_BF16(acc[mt][nt], ah[mt], b0h, b1h);
                MMA_BF16(acc[mt][nt], al[mt], b0h, b1h);
                MMA_BF16(acc[mt][nt], ah[mt], b0l, b1l);
            }
        }
    };

    loadA(0, 0); loadB(0, 0);
    asm volatile("cp.async.commit_group;\n");
    loadA(1, 1); loadB(1, 1);
    asm volatile("cp.async.commit_group;\n");
#pragma unroll
    for (int ck = 0; ck < NCH; ++ck) {
        if (ck + 1 < NCH) asm volatile("cp.async.wait_group 1;\n");
        else              asm volatile("cp.async.wait_group 0;\n");
        __syncthreads();
        if (ck + 2 < NCH) {
            loadA(ck + 2, (ck + 2) % 3); loadB(ck + 2, (ck + 2) % 3);
            asm volatile("cp.async.commit_group;\n");
        }
        compute(ck % 3);
    }

#pragma unroll
    for (int mt = 0; mt < 2; ++mt) {
        float m0 = 0.f, m1 = 0.f;
#pragma unroll
        for (int nt = 0; nt < NT; ++nt) {
            m0 = fmaxf(m0, fmaxf(fabsf(acc[mt][nt][0]), fabsf(acc[mt][nt][1])));
            m1 = fmaxf(m1, fmaxf(fabsf(acc[mt][nt][2]), fabsf(acc[mt][nt][3])));
        }
        m0 = fmaxf(m0, __shfl_xor_sync(0xFFFFFFFFu, m0, 1));
        m0 = fmaxf(m0, __shfl_xor_sync(0xFFFFFFFFu, m0, 2));
        m1 = fmaxf(m1, __shfl_xor_sync(0xFFFFFFFFu, m1, 1));
        m1 = fmaxf(m1, __shfl_xor_sync(0xFFFFFFFFu, m1, 2));
        if (tig == 0) {
            atomicMax(&rmax[wm * 32 + mt * 16 + g],     __float_as_int(m0));
            atomicMax(&rmax[wm * 32 + mt * 16 + g + 8], __float_as_int(m1));
        }
    }
    __syncthreads();
#pragma unroll
    for (int mt = 0; mt < 2; ++mt) {
        int lr0 = wm * 32 + mt * 16 + g;
        float mx0 = __int_as_float(rmax[lr0]);
        float mx1 = __int_as_float(rmax[lr0 + 8]);
        float si0 = (mx0 > 0.f) ? (32766.f / mx0) : 0.f;
        float si1 = (mx1 > 0.f) ? (32766.f / mx1) : 0.f;
        int gr0 = row0 + lr0, gr1 = gr0 + 8;
        if (wn == 0 && tig == 0) {
            if (gr0 < M) sc[gr0] = (mx0 > 0.f) ? (mx0 / 32766.f) : 0.f;
            if (gr1 < M) sc[gr1] = (mx1 > 0.f) ? (mx1 / 32766.f) : 0.f;
        }
#pragma unroll
        for (int nt = 0; nt < NT; ++nt) {
            int c = wn * 64 + nt * 8 + tig * 2;
            if (gr0 < M) {
                int a = __float2int_rn(acc[mt][nt][0] * si0);
                int b = __float2int_rn(acc[mt][nt][1] * si0);
                *(unsigned*)(q + (size_t)gr0 * BN + c) = (a & 0xFFFF) | (b << 16);
            }
            if (gr1 < M) {
                int a = __float2int_rn(acc[mt][nt][2] * si1);
                int b = __float2int_rn(acc[mt][nt][3] * si1);
                *(unsigned*)(q + (size_t)gr1 * BN + c) = (a & 0xFFFF) | (b << 16);
            }
        }
    }
}

// ---------------- batched GEMM-64 (pre-split bf16 A) + 3-vector projection ----------------
// smem: sAh[3][128][12] | sAl | sBh[3][8][72] | sBl | t3[128][4]
// SAW=12 (48B row stride, 16B-aligned for cp.async; banks 12g+tig all distinct mod 32)
__global__ __launch_bounds__(256, 2)
void k_gemm_dotb(const unsigned* __restrict__ Ah0, const unsigned* __restrict__ Al0,
                 const unsigned* __restrict__ Bh0, const unsigned* __restrict__ Bl0,
                 const float* __restrict__ ag0, float4* __restrict__ t0,
                 const unsigned* __restrict__ Ah1, const unsigned* __restrict__ Al1,
                 const unsigned* __restrict__ Bh1, const unsigned* __restrict__ Bl1,
                 const float* __restrict__ ag1v, float4* __restrict__ t1,
                 const float* __restrict__ wc, int M) {
    constexpr int BM = 128, NCH = 8, NST = 3, BN = 64, WN = 32, NT = 4;
    constexpr int SAW = 12, SBW = BN + 8;
    const int y = blockIdx.y;
    const unsigned* Ah = y ? Ah1 : Ah0;
    const unsigned* Al = y ? Al1 : Al0;
    const unsigned* Bh = y ? Bh1 : Bh0;
    const unsigned* Bl = y ? Bl1 : Bl0;
    const float*    ag = y ? ag1v : ag0;
    float4*         t  = y ? t1 : t0;

    extern __shared__ char dynsmem[];
    unsigned* sAh = (unsigned*)dynsmem;                       // NST*BM*SAW
    unsigned* sAl = sAh + NST * BM * SAW;
    unsigned* sBh = sAl + NST * BM * SAW;
    unsigned* sBl = sBh + NST * 8 * SBW;
    float*    t3  = (float*)(sBl + NST * 8 * SBW);            // 128*4

    const int tid  = threadIdx.x;
    const int wid  = tid >> 5, lane = tid & 31;
    const int wm   = wid & 3,  wn   = wid >> 2;
    const int g    = lane >> 2, tig = lane & 3;
    const int row0 = blockIdx.x * BM;

    if (tid < 128) {
        t3[tid * 4 + 0] = 0.f; t3[tid * 4 + 1] = 0.f; t3[tid * 4 + 2] = 0.f;
    }

    float acc[2][NT][4];
#pragma unroll
    for (int mt = 0; mt < 2; ++mt)
#pragma unroll
        for (int nt = 0; nt < NT; ++nt)
#pragma unroll
            for (int i = 0; i < 4; ++i) acc[mt][nt][i] = 0.f;

    auto loadA = [&](int ck, int st) {
#pragma unroll
        for (int i = 0; i < 2; ++i) {
            int item = i * 256 + tid;                // 512 items
            int half = item >> 8;                    // 0: hi, 1: lo
            int r = (item & 255) >> 1, c16 = item & 1;
            const unsigned* gp = (half ? Al : Ah) + (size_t)(row0 + r) * 64 + ck * 8 + c16 * 4;
            unsigned* sa = (half ? sAl : sAh) + (st * BM + r) * SAW + c16 * 4;
            unsigned sp = (unsigned)__cvta_generic_to_shared(sa);
            int bytes = (row0 + r < M) ? 16 : 0;
            asm volatile("cp.async.cg.shared.global [%0], [%1], 16, %2;\n"
                         :: "r"(sp), "l"(gp), "r"(bytes));
        }
    };
    auto loadB = [&](int ck, int st) {
        int half = tid >> 7;
        int t2 = tid & 127;
        int r = t2 >> 4, c4 = t2 & 15;
        const unsigned* gp = (half ? Bl : Bh) + (size_t)(ck * 8 + r) * BN + c4 * 4;
        unsigned sp = (unsigned)__cvta_generic_to_shared(
            (half ? sBl : sBh) + (st * 8 + r) * SBW + c4 * 4);
        asm volatile("cp.async.cg.shared.global [%0], [%1], 16, 16;\n" :: "r"(sp), "l"(gp));
    };
    auto compute = [&](int st) {
        unsigned ah[2][4], al[2][4];
#pragma unroll
        for (int mt = 0; mt < 2; ++mt) {
            int r = wm * 32 + mt * 16 + g;
            ah[mt][0] = sAh[(st * BM + r    ) * SAW + tig];
            ah[mt][1] = sAh[(st * BM + r + 8) * SAW + tig];
            ah[mt][2] = sAh[(st * BM + r    ) * SAW + tig + 4];
            ah[mt][3] = sAh[(st * BM + r + 8) * SAW + tig + 4];
            al[mt][0] = sAl[(st * BM + r    ) * SAW + tig];
            al[mt][1] = sAl[(st * BM + r + 8) * SAW + tig];
            al[mt][2] = sAl[(st * BM + r    ) * SAW + tig + 4];
            al[mt][3] = sAl[(st * BM + r + 8) * SAW + tig + 4];
        }
#pragma unroll
        for (int nt = 0; nt < NT; ++nt) {
            int c = wn * WN + nt * 8 + g;
            unsigned b0h = sBh[(st * 8 + tig    ) * SBW + c];
            unsigned b1h = sBh[(st * 8 + tig + 4) * SBW + c];
            unsigned b0l = sBl[(st * 8 + tig    ) * SBW + c];
            unsigned b1l = sBl[(st * 8 + tig + 4) * SBW + c];
#pragma unroll
            for (int mt = 0; mt < 2; ++mt) {
                MMA_BF16(acc[mt][nt], ah[mt], b0h, b1h);
                MMA_BF16(acc[mt][nt], al[mt], b0h, b1h);
                MMA_BF16(acc[mt][nt], ah[mt], b0l, b1l);
            }
        }
    };

    loadA(0, 0); loadB(0, 0);
    asm volatile("cp.async.commit_group;\n");
    loadA(1, 1); loadB(1, 1);
    asm volatile("cp.async.commit_group;\n");
#pragma unroll
    for (int ck = 0; ck < NCH; ++ck) {
        if (ck + 1 < NCH) asm volatile("cp.async.wait_group 1;\n");
        else              asm volatile("cp.async.wait_group 0;\n");
        __syncthreads();
        if (ck + 2 < NCH) {
            loadA(ck + 2, (ck + 2) % 3); loadB(ck + 2, (ck + 2) % 3);
            asm volatile("cp.async.commit_group;\n");
        }
        compute(ck % 3);
    }

    // projection epilogue: t[n] = (row·ag, row·w_lo, row·w_hi)
    float pa[2] = {0.f, 0.f}, pl[2] = {0.f, 0.f}, ph[2] = {0.f, 0.f};
    float pa1[2] = {0.f, 0.f}, pl1[2] = {0.f, 0.f}, ph1[2] = {0.f, 0.f};
#pragma unroll
    for (int nt = 0; nt < NT; ++nt) {
        int c = wn * WN + nt * 8 + tig * 2;
        float va0 = ag[c],      va1 = ag[c + 1];
        float vl0 = wc[c],      vl1 = wc[c + 1];
        float vh0 = wc[64 + c], vh1 = wc[64 + c + 1];
#pragma unroll
        for (int mt = 0; mt < 2; ++mt) {
            pa [mt] = fmaf(acc[mt][nt][0], va0, fmaf(acc[mt][nt][1], va1, pa [mt]));
            pl [mt] = fmaf(acc[mt][nt][0], vl0, fmaf(acc[mt][nt][1], vl1, pl [mt]));
            ph [mt] = fmaf(acc[mt][nt][0], vh0, fmaf(acc[mt][nt][1], vh1, ph [mt]));
            pa1[mt] = fmaf(acc[mt][nt][2], va0, fmaf(acc[mt][nt][3], va1, pa1[mt]));
            pl1[mt] = fmaf(acc[mt][nt][2], vl0, fmaf(acc[mt][nt][3], vl1, pl1[mt]));
            ph1[mt] = fmaf(acc[mt][nt][2], vh0, fmaf(acc[mt][nt][3], vh1, ph1[mt]));
        }
    }
#pragma unroll
    for (int mt = 0; mt < 2; ++mt) {
#pragma unroll
        for (int o = 1; o <= 2; o <<= 1) {
            pa [mt] += __shfl_xor_sync(0xFFFFFFFFu, pa [mt], o);
            pl [mt] += __shfl_xor_sync(0xFFFFFFFFu, pl [mt], o);
            ph [mt] += __shfl_xor_sync(0xFFFFFFFFu, ph [mt], o);
            pa1[mt] += __shfl_xor_sync(0xFFFFFFFFu, pa1[mt], o);
            pl1[mt] += __shfl_xor_sync(0xFFFFFFFFu, pl1[mt], o);
            ph1[mt] += __shfl_xor_sync(0xFFFFFFFFu, ph1[mt], o);
        }
        if (tig == 0) {
            int lr0 = wm * 32 + mt * 16 + g;
            atomicAdd(&t3[lr0 * 4 + 0], pa[mt]);
            atomicAdd(&t3[lr0 * 4 + 1], pl[mt]);
            atomicAdd(&t3[lr0 * 4 + 2], ph[mt]);
            atomicAdd(&t3[(lr0 + 8) * 4 + 0], pa1[mt]);
            atomicAdd(&t3[(lr0 + 8) * 4 + 1], pl1[mt]);
            atomicAdd(&t3[(lr0 + 8) * 4 + 2], ph1[mt]);
        }
    }
    __syncthreads();
    if (tid < 128) {
        int gr = row0 + tid;
        if (gr < M)
            t[gr] = make_float4(t3[tid * 4 + 0], t3[tid * 4 + 1], t3[tid * 4 + 2], 0.f);
    }
}

// ---------------- batched SpMM-128 (int16 gather, bf16-split output) ----------------
__global__ void k_spmm128b(
    const int* __restrict__ rp0, const int2* __restrict__ ep0,
    const short* __restrict__ q0, const float* __restrict__ sc0,
    const float* __restrict__ bias0, unsigned* __restrict__ oh0, unsigned* __restrict__ ol0,
    const int* __restrict__ rp1, const int2* __restrict__ ep1,
    const short* __restrict__ q1, const float* __restrict__ sc1,
    const float* __restrict__ bias1, unsigned* __restrict__ oh1, unsigned* __restrict__ ol1,
    int M) {
    const int y = blockIdx.y;
    const int*   rp   = y ? rp1 : rp0;
    const int2*  ep   = y ? ep1 : ep0;
    const short* q    = y ? q1 : q0;
    const float* sc   = y ? sc1 : sc0;
    const float* bias = y ? bias1 : bias0;
    unsigned* oh = y ? oh1 : oh0;
    unsigned* ol = y ? ol1 : ol0;

    int w = blockIdx.x * 8 + (threadIdx.x >> 5);
    if (w >= M) return;
    int l = threadIdx.x & 31;
    float4 acc = *(const float4*)(bias + l * 4);
    int p = rp[w], e = rp[w + 1];
    for (; p + 7 < e; p += 8) {
        int2 ee[8];
#pragma unroll
        for (int j = 0; j < 8; ++j) ee[j] = __ldg(&ep[p + j]);
        float cc[8];
#pragma unroll
        for (int j = 0; j < 8; ++j) cc[j] = __int_as_float(ee[j].y) * __ldg(&sc[ee[j].x]);
        int2 dd[8];
#pragma unroll
        for (int j = 0; j < 8; ++j) dd[j] = *(const int2*)(q + (size_t)ee[j].x * 128 + l * 4);
#pragma unroll
        for (int j = 0; j < 8; ++j) {
            acc.x = fmaf(cc[j], (float)((short)(dd[j].x)),       acc.x);
            acc.y = fmaf(cc[j], (float)((short)(dd[j].x >> 16)), acc.y);
            acc.z = fmaf(cc[j], (float)((short)(dd[j].y)),       acc.z);
            acc.w = fmaf(cc[j], (float)((short)(dd[j].y >> 16)), acc.w);
        }
    }
    for (; p < e; ++p) {
        int2 e0 = __ldg(&ep[p]);
        float c0 = __int_as_float(e0.y) * __ldg(&sc[e0.x]);
        int2 d0 = *(const int2*)(q + (size_t)e0.x * 128 + l * 4);
        acc.x = fmaf(c0, (float)((short)(d0.x)),       acc.x);
        acc.y = fmaf(c0, (float)((short)(d0.x >> 16)), acc.y);
        acc.z = fmaf(c0, (float)((short)(d0.y)),       acc.z);
        acc.w = fmaf(c0, (float)((short)(d0.y >> 16)), acc.w);
    }
    acc.x = fmaxf(acc.x, 0.f); acc.y = fmaxf(acc.y, 0.f);
    acc.z = fmaxf(acc.z, 0.f); acc.w = fmaxf(acc.w, 0.f);
    unsigned h0, l0, h1, l1;
    bsplit2(acc.x, acc.y, h0, l0);
    bsplit2(acc.z, acc.w, h1, l1);
    *(uint2*)(oh + (size_t)w * 64 + l * 2) = make_uint2(h0, h1);
    *(uint2*)(ol + (size_t)w * 64 + l * 2) = make_uint2(l0, l1);
}

// ---------------- batched SpMM-3 ----------------
__global__ void k_spmm3b(const int* __restrict__ rp0, const int2* __restrict__ ep0,
                         const float4* __restrict__ t0, float4* __restrict__ agg0,
                         const int* __restrict__ rp1, const int2* __restrict__ ep1,
                         const float4* __restrict__ t1, float4* __restrict__ agg1,
                         int M) {
    const int y = blockIdx.y;
    const int*    rp  = y ? rp1 : rp0;
    const int2*   ep  = y ? ep1 : ep0;
    const float4* t   = y ? t1 : t0;
    float4*       agg = y ? agg1 : agg0;

    int node = blockIdx.x * 32 + (threadIdx.x >> 3);
    int l = threadIdx.x & 7;
    bool valid = node < M;
    int p = valid ? rp[node] : 0;
    int e = valid ? rp[node + 1] : 0;
    float ax = 0.f, ay = 0.f, az = 0.f;
    for (p += l; p < e; p += 8) {
        int2 e0 = __ldg(&ep[p]);
        float c = __int_as_float(e0.y);
        float4 tv = __ldg(&t[e0.x]);
        ax = fmaf(c, tv.x, ax);
        ay = fmaf(c, tv.y, ay);
        az = fmaf(c, tv.z, az);
    }
#pragma unroll
    for (int o = 4; o > 0; o >>= 1) {
        ax += __shfl_xor_sync(0xFFFFFFFFu, ax, o, 8);
        ay += __shfl_xor_sync(0xFFFFFFFFu, ay, o, 8);
        az += __shfl_xor_sync(0xFFFFFFFFu, az, o, 8);
    }
    if (valid && l == 0) agg[node] = make_float4(ax, ay, az, 0.f);
}

// ---------------- prep: detect + wc + bias dots + packB ----------------
__global__ void k_prep(const int* __restrict__ idx32, int nwords,
                       const float* __restrict__ d1W, const float* __restrict__ d1b,
                       const float* __restrict__ d2W, const float* __restrict__ d2b,
                       const float* __restrict__ b_o2, const float* __restrict__ b_s2,
                       const float* __restrict__ ag1, const float* __restrict__ ag2,
                       float* __restrict__ wc,
                       const float* __restrict__ W1o, const float* __restrict__ W1s,
                       const float* __restrict__ W2o, const float* __restrict__ W2s,
                       unsigned* __restrict__ h1o, unsigned* __restrict__ l1o,
                       unsigned* __restrict__ h1s, unsigned* __restrict__ l1s,
                       unsigned* __restrict__ h2o, unsigned* __restrict__ l2o,
                       unsigned* __restrict__ h2s, unsigned* __restrict__ l2s) {
    int bid = blockIdx.x, tid = threadIdx.x;
    if (bid == 0) {
        if (tid < 128) {
            float s = 0.f;
#pragma unroll 8
            for (int j = 0; j < 64; ++j) s = fmaf(d1W[tid * 64 + j], d2W[j], s);
            wc[tid] = s;
            if (tid == 0) {
                float c = d2b[0];
                for (int j = 0; j < 64; ++j) c = fmaf(d1b[j], d2W[j], c);
                wc[128] = c;
            }
        } else if (tid < 160) {
            int t = tid - 128;
            int bad = 0;
#pragma unroll
            for (int j = 0; j < 4; ++j) {
                int w = (t * 4 + j) * 2 + 1;
                if (w < nwords && idx32[w] != 0) bad = 1;
            }
            unsigned m = __ballot_sync(0xFFFFFFFFu, bad);
            if (t == 0) g_i64flag = (m == 0u) ? 1 : 0;
        }
        __syncthreads();
        if ((tid >> 5) == 6) {
            int lane = tid & 31;
            for (int d = 0; d < 6; ++d) {
                const float* A = (d < 3) ? b_o2 : b_s2;
                const float* B = (d == 0) ? ag1 : (d == 3) ? ag2
                               : ((d % 3) == 1) ? wc : wc + 64;
                float v = A[lane] * B[lane] + A[lane + 32] * B[lane + 32];
#pragma unroll
                for (int o = 16; o > 0; o >>= 1)
                    v += __shfl_xor_sync(0xFFFFFFFFu, v, o);
                if (lane == 0) wc[129 + d] = v;
            }
        }
    } else {
        int idx = (bid - 1) * 256 + tid;
        const float* W; unsigned *H, *L; int BN, off;
        if (idx < 8192)       { W = W1o; H = h1o; L = l1o; BN = 128; off = idx; }
        else if (idx < 16384) { W = W1s; H = h1s; L = l1s; BN = 128; off = idx - 8192; }
        else if (idx < 20480) { W = W2o; H = h2o; L = l2o; BN = 64;  off = idx - 16384; }
        else                  { W = W2s; H = h2s; L = l2s; BN = 64;  off = idx - 20480; }
        int k2 = off / BN, n = off % BN;
        unsigned h, l;
        bsplit2(W[(2 * k2) * BN + n], W[(2 * k2 + 1) * BN + n], h, l);
        H[off] = h; L[off] = l;
    }
}

// ---------------- CSR: hist / scans / scatter ----------------
__global__ void k_hist2(const int* __restrict__ o_dst, const int* __restrict__ s_dst,
                        int* __restrict__ cntO, int* __restrict__ cntS, int E) {
    int i = blockIdx.x * blockDim.x + threadIdx.x;
    if (i < E) {
        atomicAdd(&cntO[o_dst[i]], 1);
        atomicAdd(&cntS[s_dst[i]], 1);
    }
}

__global__ void k_scan1(int* __restrict__ rp_base, int* __restrict__ bsum,
                        int n, int stride) {
    __shared__ int s[256];
    int* arr = rp_base + blockIdx.y * stride;
    int t = threadIdx.x;
    int base = blockIdx.x * 1024;
    int v[4]; int sum = 0;
#pragma unroll
    for (int j = 0; j < 4; ++j) {
        int i = base + t * 4 + j;
        v[j] = (i < n) ? arr[i] : 0;
        sum += v[j];
    }
    s[t] = sum; __syncthreads();
    for (int off = 1; off < 256; off <<= 1) {
        int x = (t >= off) ? s[t - off] : 0;
        __syncthreads();
        s[t] += x;
        __syncthreads();
    }
    int run = s[t] - sum;
    if (t == 255) bsum[blockIdx.y * 128 + blockIdx.x] = s[255];
#pragma unroll
    for (int j = 0; j < 4; ++j) {
        int i = base + t * 4 + j;
        if (i < n) arr[i] = run;
        run += v[j];
    }
}

__global__ void k_scan23(int* __restrict__ rp_base, const int* __restrict__ bsum,
                         int* __restrict__ cur_base, int n, int E, int stride) {
    int y = blockIdx.y;
    int* rp  = rp_base + y * stride;
    int* cur = cur_base + y * n;
    __shared__ int s_off;
    int i0 = blockIdx.x * blockDim.x;
    int chunk = i0 >> 10;
    if (threadIdx.x == 0) {
        int acc = 0;
        const int* bs = bsum + y * 128;
        for (int j = 0; j < chunk; ++j) acc += bs[j];
        s_off = acc;
    }
    __syncthreads();
    int i = i0 + threadIdx.x;
    if (i < n) {
        int v = rp[i] + s_off;
        rp[i] = v;
        cur[i] = v;
    } else if (i == n) {
        rp[n] = E;
    }
}

__global__ void k_scatter2(const int* __restrict__ o_dst, const int* __restrict__ o_src,
                           const float* __restrict__ o_val,
                           const int* __restrict__ s_dst, const int* __restrict__ s_src,
                           const float* __restrict__ s_val,
                           int* __restrict__ curO, int* __restrict__ curS,
                           int2* __restrict__ epO, int2* __restrict__ epS, int E) {
    int e = blockIdx.x * blockDim.x + threadIdx.x;
    if (e < E) {
        int d = o_dst[e];
        int p = atomicAdd(&curO[d], 1);
        epO[p] = make_int2(o_src[e], __float_as_int(o_val[e]));
        d = s_dst[e];
        p = atomicAdd(&curS[d], 1);
        epS[p] = make_int2(s_src[e], __float_as_int(s_val[e]));
    }
}

// ---------------- gate + pair output ----------------
__global__ void k_gate3(const float4* __restrict__ aggO, const float4* __restrict__ aggS,
                        const float* __restrict__ wc, float* __restrict__ ga,
                        float* __restrict__ gb, int N) {
    int n = blockIdx.x * blockDim.x + threadIdx.x;
    if (n >= N) return;
    float4 aO = aggO[n], aS = aggS[n];
    float g1  = aO.x + wc[129];
    float xl1 = aO.y + wc[130];
    float xh1 = aO.z + wc[131];
    float g2  = aS.x + wc[132];
    float xl2 = aS.y + wc[133];
    float xh2 = aS.z + wc[134];
    ga[n] = g1 * xl1 + g2 * xl2;
    gb[n] = g1 * xh1 + g2 * xh2;
}

__global__ void k_final(const void* __restrict__ idxv, const float* __restrict__ ga,
                        const float* __restrict__ gb, const float* __restrict__ wc,
                        float* __restrict__ out, int P, int N) {
    int p = blockIdx.x * blockDim.x + threadIdx.x;
    if (p >= P) return;
    long long i0, i1;
    if (g_i64flag) {
        const long long* qq = (const long long*)idxv;
        i0 = qq[p]; i1 = qq[(size_t)P + p];
    } else {
        const int* qq = (const int*)idxv;
        i0 = qq[p]; i1 = qq[(size_t)P + p];
    }
    i0 = i0 < 0 ? 0 : (i0 >= N ? N - 1 : i0);
    i1 = i1 < 0 ? 0 : (i1 >= N ? N - 1 : i1);
    out[p] = ga[i0] + gb[i1] + wc[128];
}

// ---------------- host ----------------
extern "C" void kernel_launch(void* const* d_in, const int* in_sizes, int n_in,
                              void* d_out, int out_size) {
    const float* x       = (const float*)d_in[0];
    const int*   o_edges = (const int*)d_in[1];
    const float* o_vals  = (const float*)d_in[2];
    const int*   s_edges = (const int*)d_in[3];
    const float* s_vals  = (const float*)d_in[4];
    const void*  idx     = d_in[5];
    const float* W_o1 = (const float*)d_in[6];
    const float* b_o1 = (const float*)d_in[7];
    const float* W_o2 = (const float*)d_in[8];
    const float* b_o2 = (const float*)d_in[9];
    const float* W_s1 = (const float*)d_in[10];
    const float* b_s1 = (const float*)d_in[11];
    const float* W_s2 = (const float*)d_in[12];
    const float* b_s2 = (const float*)d_in[13];
    const float* ag1  = (const float*)d_in[14];
    const float* ag2  = (const float*)d_in[15];
    const float* d1W  = (const float*)d_in[16];
    const float* d1b  = (const float*)d_in[17];
    const float* d2W  = (const float*)d_in[18];
    const float* d2b  = (const float*)d_in[19];
    float* out = (float*)d_out;

    const int N = in_sizes[0] / 128;
    const int E = in_sizes[2];
    const int P = in_sizes[5] / 2;

    float *s1o, *s1s, *ga, *gb, *wc;
    short *q1o, *q1s;
    unsigned *hoh, *hol, *hsh, *hsl;
    float4 *tO, *tS, *aggO, *aggS;
    int *rp, *cur, *bsum;
    int2 *ep;
    unsigned *h1o, *l1o, *h1s, *l1s, *h2o, *l2o, *h2s, *l2s;
    cudaGetSymbolAddress((void**)&hoh,  g_hoh);
    cudaGetSymbolAddress((void**)&hol,  g_hol);
    cudaGetSymbolAddress((void**)&hsh,  g_hsh);
    cudaGetSymbolAddress((void**)&hsl,  g_hsl);
    cudaGetSymbolAddress((void**)&q1o,  g_q1o);
    cudaGetSymbolAddress((void**)&q1s,  g_q1s);
    cudaGetSymbolAddress((void**)&s1o,  g_s1o);
    cudaGetSymbolAddress((void**)&s1s,  g_s1s);
    cudaGetSymbolAddress((void**)&tO,   g_tO);
    cudaGetSymbolAddress((void**)&tS,   g_tS);
    cudaGetSymbolAddress((void**)&aggO, g_aggO);
    cudaGetSymbolAddress((void**)&aggS, g_aggS);
    cudaGetSymbolAddress((void**)&ga,   g_av);
    cudaGetSymbolAddress((void**)&gb,   g_bv);
    cudaGetSymbolAddress((void**)&wc,   g_wc);
    cudaGetSymbolAddress((void**)&rp,   g_rp);
    cudaGetSymbolAddress((void**)&ep,   g_ep);
    cudaGetSymbolAddress((void**)&cur,  g_cur);
    cudaGetSymbolAddress((void**)&bsum, g_bsum);
    cudaGetSymbolAddress((void**)&h1o,  g_Wh1o);
    cudaGetSymbolAddress((void**)&l1o,  g_Wl1o);
    cudaGetSymbolAddress((void**)&h1s,  g_Wh1s);
    cudaGetSymbolAddress((void**)&l1s,  g_Wl1s);
    cudaGetSymbolAddress((void**)&h2o,  g_Wh2o);
    cudaGetSymbolAddress((void**)&l2o,  g_Wl2o);
    cudaGetSymbolAddress((void**)&h2s,  g_Wh2s);
    cudaGetSymbolAddress((void**)&l2s,  g_Wl2s);

    int* rpO = rp;
    int* rpS = rp + (N + 1);
    int* curO = cur;
    int* curS = cur + N;
    int2* epO = ep;
    int2* epS = ep + E;

    const int nb   = (N + 1023) / 1024;
    const int GB   = (N + 127) / 128;
    const int SB   = (E + 255) / 256;
    const int SPB  = (N + 7) / 8;
    const int S3B  = (N + 31) / 32;
    const int rp_n = 2 * (N + 1);

    const int SM128 = 3 * 128 * 20 * 4 + 2 * 3 * 8 * 136 * 4 + 512;          // 57344
    const int SMDOT = 2 * 3 * 128 * 12 * 4 + 2 * 3 * 8 * 72 * 4 + 2048;      // 52736
    cudaFuncSetAttribute(k_gemm_q128, cudaFuncAttributeMaxDynamicSharedMemorySize, SM128);
    cudaFuncSetAttribute(k_gemm_dotb, cudaFuncAttributeMaxDynamicSharedMemorySize, SMDOT);

    const bool conc = g_sr.ok;
    cudaStream_t sB = conc ? g_sr.sB : 0;

    int nwords = in_sizes[5];
    int probe = nwords < 256 ? nwords : 256;

    // First op MUST be on stream0 (the capture stream); fork sB from it so the
    // sB branch is part of the captured graph.
    cudaMemsetAsync(rp, 0, (size_t)rp_n * sizeof(int), 0);
    if (conc) {
        cudaEventRecord(g_sr.evFork, 0);
        cudaStreamWaitEvent(sB, g_sr.evFork, 0);
    }

    // sB (or stream0 serial fallback): prep + layer-1 GEMMs
    k_prep<<<97, 256, 0, sB>>>((const int*)idx, probe, d1W, d1b, d2W, d2b,
                               b_o2, b_s2, ag1, ag2, wc,
                               W_o1, W_s1, W_o2, W_s2,
                               h1o, l1o, h1s, l1s, h2o, l2o, h2s, l2s);
    k_gemm_q128<<<GB, 256, SM128, sB>>>(x, h1o, l1o, q1o, s1o, N);
    k_gemm_q128<<<GB, 256, SM128, sB>>>(x, h1s, l1s, q1s, s1s, N);
    if (conc) cudaEventRecord(g_sr.evG1, sB);

    // stream0: CSR chain (concurrent with sB when available)
    k_hist2<<<SB, 256>>>(o_edges, s_edges, rpO, rpS, E);
    { dim3 g(nb, 2); k_scan1<<<g, 256>>>(rp, bsum, N, N + 1); }
    { dim3 g((N + 1 + 255) / 256, 2); k_scan23<<<g, 256>>>(rp, bsum, cur, N, E, N + 1); }
    k_scatter2<<<SB, 256>>>(o_edges, o_edges + E, o_vals,
                            s_edges, s_edges + E, s_vals,
                            curO, curS, epO, epS, E);
    if (conc) cudaStreamWaitEvent(0, g_sr.evG1, 0);   // join: stream0 needs q1*/s1*

    // batched phase 3 (full-device, single stream)
    { dim3 g(SPB, 2);
      k_spmm128b<<<g, 256>>>(rpO, epO, q1o, s1o, b_o1, hoh, hol,
                             rpS, epS, q1s, s1s, b_s1, hsh, hsl, N); }
    { dim3 g(GB, 2);
      k_gemm_dotb<<<g, 256, SMDOT>>>(hoh, hol, h2o, l2o, ag1, tO,
                                     hsh, hsl, h2s, l2s, ag2, tS, wc, N); }
    { dim3 g(S3B, 2);
      k_spmm3b<<<g, 256>>>(rpO, epO, tO, aggO, rpS, epS, tS, aggS, N); }

    // tail
    k_gate3<<<(N + 255) / 256, 256>>>(aggO, aggS, wc, ga, gb, N);
    k_final<<<(P + 255) / 256, 256>>>(idx, ga, gb, wc, out, P, N);
}

// round 16
// speedup vs baseline: 1.0698x; 1.0698x over previous
#include <cuda_runtime.h>
#include <cuda_bf16.h>

#define NMAX 100000
#define EMAX 1600000

// ---------------- scratch ----------------
static __device__ __align__(16) unsigned g_hoh[ (size_t)NMAX*64 ];
static __device__ __align__(16) unsigned g_hol[ (size_t)NMAX*64 ];
static __device__ __align__(16) unsigned g_hsh[ (size_t)NMAX*64 ];
static __device__ __align__(16) unsigned g_hsl[ (size_t)NMAX*64 ];
static __device__ __align__(16) short  g_q1o [ (size_t)NMAX*128 ];
static __device__ __align__(16) short  g_q1s [ (size_t)NMAX*128 ];
static __device__ __align__(16) float  g_s1o [ NMAX ];
static __device__ __align__(16) float  g_s1s [ NMAX ];
static __device__ __align__(16) float4 g_tO  [ NMAX ];
static __device__ __align__(16) float4 g_tS  [ NMAX ];
static __device__ __align__(16) float4 g_aggO[ NMAX ];
static __device__ __align__(16) float4 g_aggS[ NMAX ];
static __device__ __align__(16) float  g_av  [ NMAX ];
static __device__ __align__(16) float  g_bv  [ NMAX ];
static __device__ __align__(16) float  g_wc  [ 144 ];
static __device__ __align__(16) int    g_rp  [ 2*(NMAX+1) ];
static __device__ __align__(16) int2   g_ep  [ (size_t)2*EMAX ];
static __device__ __align__(16) int    g_cur [ 2*NMAX ];
static __device__ __align__(16) int    g_bsum[ 256 ];
static __device__ __align__(16) unsigned g_Wh1o[64*128], g_Wl1o[64*128];
static __device__ __align__(16) unsigned g_Wh1s[64*128], g_Wl1s[64*128];
static __device__ __align__(16) unsigned g_Wh2o[64*64],  g_Wl2o[64*64];
static __device__ __align__(16) unsigned g_Wh2s[64*64],  g_Wl2s[64*64];
static __device__            int   g_i64flag;

// ---------------- stream/event resources (static init) ----------------
struct StreamRes {
    cudaStream_t sB;
    cudaEvent_t evFork, evG1, evCSR, evS;
    bool ok;
    StreamRes() : sB(0), evFork(0), evG1(0), evCSR(0), evS(0), ok(false) {
        if (cudaStreamCreate(&sB) != cudaSuccess) { sB = 0; return; }
        if (cudaEventCreateWithFlags(&evFork, cudaEventDisableTiming) != cudaSuccess) return;
        if (cudaEventCreateWithFlags(&evG1,   cudaEventDisableTiming) != cudaSuccess) return;
        if (cudaEventCreateWithFlags(&evCSR,  cudaEventDisableTiming) != cudaSuccess) return;
        if (cudaEventCreateWithFlags(&evS,    cudaEventDisableTiming) != cudaSuccess) return;
        ok = true;
    }
};
static StreamRes g_sr;

// ---------------- bf16 hi/lo split ----------------
__device__ __forceinline__ void bsplit2(float x0, float x1, unsigned& h, unsigned& l) {
    unsigned hp;
    asm("cvt.rn.bf16x2.f32 %0, %1, %2;" : "=r"(hp) : "f"(x1), "f"(x0));
    float fh0 = __uint_as_float(hp << 16);
    float fh1 = __uint_as_float(hp & 0xFFFF0000u);
    float r0 = x0 - fh0, r1 = x1 - fh1;
    asm("cvt.rn.bf16x2.f32 %0, %1, %2;" : "=r"(l) : "f"(r1), "f"(r0));
    h = hp;
}

#define MMA_BF16(acc, a, b0, b1)                                              \
    asm volatile(                                                             \
        "mma.sync.aligned.m16n8k16.row.col.f32.bf16.bf16.f32 "                \
        "{%0,%1,%2,%3}, {%4,%5,%6,%7}, {%8,%9}, {%0,%1,%2,%3};\n"             \
        : "+f"(acc[0]), "+f"(acc[1]), "+f"(acc[2]), "+f"(acc[3])              \
        : "r"(a[0]), "r"(a[1]), "r"(a[2]), "r"(a[3]), "r"(b0), "r"(b1))

// ---------------- GEMM-128 (fp32 A, in-kernel split) + int16 rowquant ----------------
__global__ __launch_bounds__(256, 2)
void k_gemm_q128(const float* __restrict__ A,
                 const unsigned* __restrict__ Bh, const unsigned* __restrict__ Bl,
                 short* __restrict__ q, float* __restrict__ sc, int M) {
    constexpr int BM = 128, BK = 16, KTOT = 128, NCH = KTOT / BK, NST = 3;
    constexpr int BN = 128, WN = 64, NT = 8;
    constexpr int SAW = BK + 4, SBW = BN + 8;
    extern __shared__ char dynsmem[];
    float*    sA   = (float*)dynsmem;
    unsigned* sBh  = (unsigned*)(dynsmem + NST * BM * SAW * 4);
    unsigned* sBl  = sBh + NST * 8 * SBW;
    int*      rmax = (int*)(sBl + NST * 8 * SBW);

    const int tid  = threadIdx.x;
    const int wid  = tid >> 5, lane = tid & 31;
    const int wm   = wid & 3,  wn   = wid >> 2;
    const int g    = lane >> 2, tig = lane & 3;
    const int row0 = blockIdx.x * BM;

    if (tid < BM) rmax[tid] = 0;

    float acc[2][NT][4];
#pragma unroll
    for (int mt = 0; mt < 2; ++mt)
#pragma unroll
        for (int nt = 0; nt < NT; ++nt)
#pragma unroll
            for (int i = 0; i < 4; ++i) acc[mt][nt][i] = 0.f;

    auto loadA = [&](int ck, int st) {
#pragma unroll
        for (int i = 0; i < 2; ++i) {
            int idx = i * 256 + tid;
            int r = idx >> 2, c4 = idx & 3;
            const float* gp = A + (size_t)(row0 + r) * KTOT + ck * BK + c4 * 4;
            unsigned sp = (unsigned)__cvta_generic_to_shared(&sA[(st * BM + r) * SAW + c4 * 4]);
            int bytes = (row0 + r < M) ? 16 : 0;
            asm volatile("cp.async.cg.shared.global [%0], [%1], 16, %2;\n"
                         :: "r"(sp), "l"(gp), "r"(bytes));
        }
    };
    auto loadB = [&](int ck, int st) {
        int r = tid >> 5, c4 = tid & 31;
        const unsigned* gh = Bh + (size_t)(ck * 8 + r) * BN + c4 * 4;
        const unsigned* gl = Bl + (size_t)(ck * 8 + r) * BN + c4 * 4;
        unsigned sph = (unsigned)__cvta_generic_to_shared(&sBh[(st * 8 + r) * SBW + c4 * 4]);
        unsigned spl = (unsigned)__cvta_generic_to_shared(&sBl[(st * 8 + r) * SBW + c4 * 4]);
        asm volatile("cp.async.cg.shared.global [%0], [%1], 16, 16;\n" :: "r"(sph), "l"(gh));
        asm volatile("cp.async.cg.shared.global [%0], [%1], 16, 16;\n" :: "r"(spl), "l"(gl));
    };
    auto compute = [&](int st) {
        unsigned ah[2][4], al[2][4];
#pragma unroll
        for (int mt = 0; mt < 2; ++mt) {
            int r = wm * 32 + mt * 16 + g;
            float2 p0 = *(const float2*)&sA[(st * BM + r    ) * SAW + 2 * tig];
            float2 p1 = *(const float2*)&sA[(st * BM + r + 8) * SAW + 2 * tig];
            float2 p2 = *(const float2*)&sA[(st * BM + r    ) * SAW + 2 * tig + 8];
            float2 p3 = *(const float2*)&sA[(st * BM + r + 8) * SAW + 2 * tig + 8];
            bsplit2(p0.x, p0.y, ah[mt][0], al[mt][0]);
            bsplit2(p1.x, p1.y, ah[mt][1], al[mt][1]);
            bsplit2(p2.x, p2.y, ah[mt][2], al[mt][2]);
            bsplit2(p3.x, p3.y, ah[mt][3], al[mt][3]);
        }
#pragma unroll
        for (int nt = 0; nt < NT; ++nt) {
            int c = wn * WN + nt * 8 + g;
            unsigned b0h = sBh[(st * 8 + tig    ) * SBW + c];
            unsigned b1h = sBh[(st * 8 + tig + 4) * SBW + c];
            unsigned b0l = sBl[(st * 8 + tig    ) * SBW + c];
            unsigned b1l = sBl[(st * 8 + tig + 4) * SBW + c];
#pragma unroll
            for (int mt = 0; mt < 2; ++mt) {
                MMA_BF16(acc[mt][nt], ah[mt], b0h, b1h);
                MMA_BF16(acc[mt][nt], al[mt], b0h, b1h);
                MMA_BF16(acc[mt][nt], ah[mt], b0l, b1l);
            }
        }
    };

    loadA(0, 0); loadB(0, 0);
    asm volatile("cp.async.commit_group;\n");
    loadA(1, 1); loadB(1, 1);
    asm volatile("cp.async.commit_group;\n");
#pragma unroll
    for (int ck = 0; ck < NCH; ++ck) {
        if (ck + 1 < NCH) asm volatile("cp.async.wait_group 1;\n");
        else              asm volatile("cp.async.wait_group 0;\n");
        __syncthreads();
        if (ck + 2 < NCH) {
            loadA(ck + 2, (ck + 2) % 3); loadB(ck + 2, (ck + 2) % 3);
            asm volatile("cp.async.commit_group;\n");
        }
        compute(ck % 3);
    }

#pragma unroll
    for (int mt = 0; mt < 2; ++mt) {
        float m0 = 0.f, m1 = 0.f;
#pragma unroll
        for (int nt = 0; nt < NT; ++nt) {
            m0 = fmaxf(m0, fmaxf(fabsf(acc[mt][nt][0]), fabsf(acc[mt][nt][1])));
            m1 = fmaxf(m1, fmaxf(fabsf(acc[mt][nt][2]), fabsf(acc[mt][nt][3])));
        }
        m0 = fmaxf(m0, __shfl_xor_sync(0xFFFFFFFFu, m0, 1));
        m0 = fmaxf(m0, __shfl_xor_sync(0xFFFFFFFFu, m0, 2));
        m1 = fmaxf(m1, __shfl_xor_sync(0xFFFFFFFFu, m1, 1));
        m1 = fmaxf(m1, __shfl_xor_sync(0xFFFFFFFFu, m1, 2));
        if (tig == 0) {
            atomicMax(&rmax[wm * 32 + mt * 16 + g],     __float_as_int(m0));
            atomicMax(&rmax[wm * 32 + mt * 16 + g + 8], __float_as_int(m1));
        }
    }
    __syncthreads();
#pragma unroll
    for (int mt = 0; mt < 2; ++mt) {
        int lr0 = wm * 32 + mt * 16 + g;
        float mx0 = __int_as_float(rmax[lr0]);
        float mx1 = __int_as_float(rmax[lr0 + 8]);
        float si0 = (mx0 > 0.f) ? (32766.f / mx0) : 0.f;
        float si1 = (mx1 > 0.f) ? (32766.f / mx1) : 0.f;
        int gr0 = row0 + lr0, gr1 = gr0 + 8;
        if (wn == 0 && tig == 0) {
            if (gr0 < M) sc[gr0] = (mx0 > 0.f) ? (mx0 / 32766.f) : 0.f;
            if (gr1 < M) sc[gr1] = (mx1 > 0.f) ? (mx1 / 32766.f) : 0.f;
        }
#pragma unroll
        for (int nt = 0; nt < NT; ++nt) {
            int c = wn * 64 + nt * 8 + tig * 2;
            if (gr0 < M) {
                int a = __float2int_rn(acc[mt][nt][0] * si0);
                int b = __float2int_rn(acc[mt][nt][1] * si0);
                *(unsigned*)(q + (size_t)gr0 * BN + c) = (a & 0xFFFF) | (b << 16);
            }
            if (gr1 < M) {
                int a = __float2int_rn(acc[mt][nt][2] * si1);
                int b = __float2int_rn(acc[mt][nt][3] * si1);
                *(unsigned*)(q + (size_t)gr1 * BN + c) = (a & 0xFFFF) | (b << 16);
            }
        }
    }
}

// ---------------- GEMM-64 (pre-split bf16 A) + 3-vector projection ----------------
// smem: sAh[3][128][12] | sAl | sBh[3][8][72] | sBl | t3[128][4]
__global__ __launch_bounds__(256, 2)
void k_gemm_dot(const unsigned* __restrict__ Ah, const unsigned* __restrict__ Al,
                const unsigned* __restrict__ Bh, const unsigned* __restrict__ Bl,
                const float* __restrict__ ag, float4* __restrict__ t,
                const float* __restrict__ wc, int M) {
    constexpr int BM = 128, NCH = 8, NST = 3, BN = 64, WN = 32, NT = 4;
    constexpr int SAW = 12, SBW = BN + 8;
    extern __shared__ char dynsmem[];
    unsigned* sAh = (unsigned*)dynsmem;
    unsigned* sAl = sAh + NST * BM * SAW;
    unsigned* sBh = sAl + NST * BM * SAW;
    unsigned* sBl = sBh + NST * 8 * SBW;
    float*    t3  = (float*)(sBl + NST * 8 * SBW);

    const int tid  = threadIdx.x;
    const int wid  = tid >> 5, lane = tid & 31;
    const int wm   = wid & 3,  wn   = wid >> 2;
    const int g    = lane >> 2, tig = lane & 3;
    const int row0 = blockIdx.x * BM;

    if (tid < 128) {
        t3[tid * 4 + 0] = 0.f; t3[tid * 4 + 1] = 0.f; t3[tid * 4 + 2] = 0.f;
    }

    float acc[2][NT][4];
#pragma unroll
    for (int mt = 0; mt < 2; ++mt)
#pragma unroll
        for (int nt = 0; nt < NT; ++nt)
#pragma unroll
            for (int i = 0; i < 4; ++i) acc[mt][nt][i] = 0.f;

    auto loadA = [&](int ck, int st) {
#pragma unroll
        for (int i = 0; i < 2; ++i) {
            int item = i * 256 + tid;
            int half = item >> 8;
            int r = (item & 255) >> 1, c16 = item & 1;
            const unsigned* gp = (half ? Al : Ah) + (size_t)(row0 + r) * 64 + ck * 8 + c16 * 4;
            unsigned* sa = (half ? sAl : sAh) + (st * BM + r) * SAW + c16 * 4;
            unsigned sp = (unsigned)__cvta_generic_to_shared(sa);
            int bytes = (row0 + r < M) ? 16 : 0;
            asm volatile("cp.async.cg.shared.global [%0], [%1], 16, %2;\n"
                         :: "r"(sp), "l"(gp), "r"(bytes));
        }
    };
    auto loadB = [&](int ck, int st) {
        int half = tid >> 7;
        int t2 = tid & 127;
        int r = t2 >> 4, c4 = t2 & 15;
        const unsigned* gp = (half ? Bl : Bh) + (size_t)(ck * 8 + r) * BN + c4 * 4;
        unsigned sp = (unsigned)__cvta_generic_to_shared(
            (half ? sBl : sBh) + (st * 8 + r) * SBW + c4 * 4);
        asm volatile("cp.async.cg.shared.global [%0], [%1], 16, 16;\n" :: "r"(sp), "l"(gp));
    };
    auto compute = [&](int st) {
        unsigned ah[2][4], al[2][4];
#pragma unroll
        for (int mt = 0; mt < 2; ++mt) {
            int r = wm * 32 + mt * 16 + g;
            ah[mt][0] = sAh[(st * BM + r    ) * SAW + tig];
            ah[mt][1] = sAh[(st * BM + r + 8) * SAW + tig];
            ah[mt][2] = sAh[(st * BM + r    ) * SAW + tig + 4];
            ah[mt][3] = sAh[(st * BM + r + 8) * SAW + tig + 4];
            al[mt][0] = sAl[(st * BM + r    ) * SAW + tig];
            al[mt][1] = sAl[(st * BM + r + 8) * SAW + tig];
            al[mt][2] = sAl[(st * BM + r    ) * SAW + tig + 4];
            al[mt][3] = sAl[(st * BM + r + 8) * SAW + tig + 4];
        }
#pragma unroll
        for (int nt = 0; nt < NT; ++nt) {
            int c = wn * WN + nt * 8 + g;
            unsigned b0h = sBh[(st * 8 + tig    ) * SBW + c];
            unsigned b1h = sBh[(st * 8 + tig + 4) * SBW + c];
            unsigned b0l = sBl[(st * 8 + tig    ) * SBW + c];
            unsigned b1l = sBl[(st * 8 + tig + 4) * SBW + c];
#pragma unroll
            for (int mt = 0; mt < 2; ++mt) {
                MMA_BF16(acc[mt][nt], ah[mt], b0h, b1h);
                MMA_BF16(acc[mt][nt], al[mt], b0h, b1h);
                MMA_BF16(acc[mt][nt], ah[mt], b0l, b1l);
            }
        }
    };

    loadA(0, 0); loadB(0, 0);
    asm volatile("cp.async.commit_group;\n");
    loadA(1, 1); loadB(1, 1);
    asm volatile("cp.async.commit_group;\n");
#pragma unroll
    for (int ck = 0; ck < NCH; ++ck) {
        if (ck + 1 < NCH) asm volatile("cp.async.wait_group 1;\n");
        else              asm volatile("cp.async.wait_group 0;\n");
        __syncthreads();
        if (ck + 2 < NCH) {
            loadA(ck + 2, (ck + 2) % 3); loadB(ck + 2, (ck + 2) % 3);
            asm volatile("cp.async.commit_group;\n");
        }
        compute(ck % 3);
    }

    float pa[2] = {0.f, 0.f}, pl[2] = {0.f, 0.f}, ph[2] = {0.f, 0.f};
    float pa1[2] = {0.f, 0.f}, pl1[2] = {0.f, 0.f}, ph1[2] = {0.f, 0.f};
#pragma unroll
    for (int nt = 0; nt < NT; ++nt) {
        int c = wn * WN + nt * 8 + tig * 2;
        float va0 = ag[c],      va1 = ag[c + 1];
        float vl0 = wc[c],      vl1 = wc[c + 1];
        float vh0 = wc[64 + c], vh1 = wc[64 + c + 1];
#pragma unroll
        for (int mt = 0; mt < 2; ++mt) {
            pa [mt] = fmaf(acc[mt][nt][0], va0, fmaf(acc[mt][nt][1], va1, pa [mt]));
            pl [mt] = fmaf(acc[mt][nt][0], vl0, fmaf(acc[mt][nt][1], vl1, pl [mt]));
            ph [mt] = fmaf(acc[mt][nt][0], vh0, fmaf(acc[mt][nt][1], vh1, ph [mt]));
            pa1[mt] = fmaf(acc[mt][nt][2], va0, fmaf(acc[mt][nt][3], va1, pa1[mt]));
            pl1[mt] = fmaf(acc[mt][nt][2], vl0, fmaf(acc[mt][nt][3], vl1, pl1[mt]));
            ph1[mt] = fmaf(acc[mt][nt][2], vh0, fmaf(acc[mt][nt][3], vh1, ph1[mt]));
        }
    }
#pragma unroll
    for (int mt = 0; mt < 2; ++mt) {
#pragma unroll
        for (int o = 1; o <= 2; o <<= 1) {
            pa [mt] += __shfl_xor_sync(0xFFFFFFFFu, pa [mt], o);
            pl [mt] += __shfl_xor_sync(0xFFFFFFFFu, pl [mt], o);
            ph [mt] += __shfl_xor_sync(0xFFFFFFFFu, ph [mt], o);
            pa1[mt] += __shfl_xor_sync(0xFFFFFFFFu, pa1[mt], o);
            pl1[mt] += __shfl_xor_sync(0xFFFFFFFFu, pl1[mt], o);
            ph1[mt] += __shfl_xor_sync(0xFFFFFFFFu, ph1[mt], o);
        }
        if (tig == 0) {
            int lr0 = wm * 32 + mt * 16 + g;
            atomicAdd(&t3[lr0 * 4 + 0], pa[mt]);
            atomicAdd(&t3[lr0 * 4 + 1], pl[mt]);
            atomicAdd(&t3[lr0 * 4 + 2], ph[mt]);
            atomicAdd(&t3[(lr0 + 8) * 4 + 0], pa1[mt]);
            atomicAdd(&t3[(lr0 + 8) * 4 + 1], pl1[mt]);
            atomicAdd(&t3[(lr0 + 8) * 4 + 2], ph1[mt]);
        }
    }
    __syncthreads();
    if (tid < 128) {
        int gr = row0 + tid;
        if (gr < M)
            t[gr] = make_float4(t3[tid * 4 + 0], t3[tid * 4 + 1], t3[tid * 4 + 2], 0.f);
    }
}

// ---------------- SpMM-128 (int16 gather, bf16-split output) ----------------
__global__ void k_spmm128(const int* __restrict__ rp, const int2* __restrict__ ep,
                          const short* __restrict__ q, const float* __restrict__ sc,
                          const float* __restrict__ bias,
                          unsigned* __restrict__ oh, unsigned* __restrict__ ol, int M) {
    int w = blockIdx.x * 8 + (threadIdx.x >> 5);
    if (w >= M) return;
    int l = threadIdx.x & 31;
    float4 acc = *(const float4*)(bias + l * 4);
    int p = rp[w], e = rp[w + 1];
    for (; p + 7 < e; p += 8) {
        int2 ee[8];
#pragma unroll
        for (int j = 0; j < 8; ++j) ee[j] = __ldg(&ep[p + j]);
        float cc[8];
#pragma unroll
        for (int j = 0; j < 8; ++j) cc[j] = __int_as_float(ee[j].y) * __ldg(&sc[ee[j].x]);
        int2 dd[8];
#pragma unroll
        for (int j = 0; j < 8; ++j) dd[j] = *(const int2*)(q + (size_t)ee[j].x * 128 + l * 4);
#pragma unroll
        for (int j = 0; j < 8; ++j) {
            acc.x = fmaf(cc[j], (float)((short)(dd[j].x)),       acc.x);
            acc.y = fmaf(cc[j], (float)((short)(dd[j].x >> 16)), acc.y);
            acc.z = fmaf(cc[j], (float)((short)(dd[j].y)),       acc.z);
            acc.w = fmaf(cc[j], (float)((short)(dd[j].y >> 16)), acc.w);
        }
    }
    for (; p < e; ++p) {
        int2 e0 = __ldg(&ep[p]);
        float c0 = __int_as_float(e0.y) * __ldg(&sc[e0.x]);
        int2 d0 = *(const int2*)(q + (size_t)e0.x * 128 + l * 4);
        acc.x = fmaf(c0, (float)((short)(d0.x)),       acc.x);
        acc.y = fmaf(c0, (float)((short)(d0.x >> 16)), acc.y);
        acc.z = fmaf(c0, (float)((short)(d0.y)),       acc.z);
        acc.w = fmaf(c0, (float)((short)(d0.y >> 16)), acc.w);
    }
    acc.x = fmaxf(acc.x, 0.f); acc.y = fmaxf(acc.y, 0.f);
    acc.z = fmaxf(acc.z, 0.f); acc.w = fmaxf(acc.w, 0.f);
    unsigned h0, l0, h1, l1;
    bsplit2(acc.x, acc.y, h0, l0);
    bsplit2(acc.z, acc.w, h1, l1);
    *(uint2*)(oh + (size_t)w * 64 + l * 2) = make_uint2(h0, h1);
    *(uint2*)(ol + (size_t)w * 64 + l * 2) = make_uint2(l0, l1);
}

// ---------------- SpMM-3 ----------------
__global__ void k_spmm3(const int* __restrict__ rp, const int2* __restrict__ ep,
                        const float4* __restrict__ t, float4* __restrict__ agg, int M) {
    int node = blockIdx.x * 32 + (threadIdx.x >> 3);
    int l = threadIdx.x & 7;
    bool valid = node < M;
    int p = valid ? rp[node] : 0;
    int e = valid ? rp[node + 1] : 0;
    float ax = 0.f, ay = 0.f, az = 0.f;
    for (p += l; p < e; p += 8) {
        int2 e0 = __ldg(&ep[p]);
        float c = __int_as_float(e0.y);
        float4 tv = __ldg(&t[e0.x]);
        ax = fmaf(c, tv.x, ax);
        ay = fmaf(c, tv.y, ay);
        az = fmaf(c, tv.z, az);
    }
#pragma unroll
    for (int o = 4; o > 0; o >>= 1) {
        ax += __shfl_xor_sync(0xFFFFFFFFu, ax, o, 8);
        ay += __shfl_xor_sync(0xFFFFFFFFu, ay, o, 8);
        az += __shfl_xor_sync(0xFFFFFFFFu, az, o, 8);
    }
    if (valid && l == 0) agg[node] = make_float4(ax, ay, az, 0.f);
}

// ---------------- prep: detect + wc + bias dots + packB ----------------
__global__ void k_prep(const int* __restrict__ idx32, int nwords,
                       const float* __restrict__ d1W, const float* __restrict__ d1b,
                       const float* __restrict__ d2W, const float* __restrict__ d2b,
                       const float* __restrict__ b_o2, const float* __restrict__ b_s2,
                       const float* __restrict__ ag1, const float* __restrict__ ag2,
                       float* __restrict__ wc,
                       const float* __restrict__ W1o, const float* __restrict__ W1s,
                       const float* __restrict__ W2o, const float* __restrict__ W2s,
                       unsigned* __restrict__ h1o, unsigned* __restrict__ l1o,
                       unsigned* __restrict__ h1s, unsigned* __restrict__ l1s,
                       unsigned* __restrict__ h2o, unsigned* __restrict__ l2o,
                       unsigned* __restrict__ h2s, unsigned* __restrict__ l2s) {
    int bid = blockIdx.x, tid = threadIdx.x;
    if (bid == 0) {
        if (tid < 128) {
            float s = 0.f;
#pragma unroll 8
            for (int j = 0; j < 64; ++j) s = fmaf(d1W[tid * 64 + j], d2W[j], s);
            wc[tid] = s;
            if (tid == 0) {
                float c = d2b[0];
                for (int j = 0; j < 64; ++j) c = fmaf(d1b[j], d2W[j], c);
                wc[128] = c;
            }
        } else if (tid < 160) {
            int t = tid - 128;
            int bad = 0;
#pragma unroll
            for (int j = 0; j < 4; ++j) {
                int w = (t * 4 + j) * 2 + 1;
                if (w < nwords && idx32[w] != 0) bad = 1;
            }
            unsigned m = __ballot_sync(0xFFFFFFFFu, bad);
            if (t == 0) g_i64flag = (m == 0u) ? 1 : 0;
        }
        __syncthreads();
        if ((tid >> 5) == 6) {
            int lane = tid & 31;
            for (int d = 0; d < 6; ++d) {
                const float* A = (d < 3) ? b_o2 : b_s2;
                const float* B = (d == 0) ? ag1 : (d == 3) ? ag2
                               : ((d % 3) == 1) ? wc : wc + 64;
                float v = A[lane] * B[lane] + A[lane + 32] * B[lane + 32];
#pragma unroll
                for (int o = 16; o > 0; o >>= 1)
                    v += __shfl_xor_sync(0xFFFFFFFFu, v, o);
                if (lane == 0) wc[129 + d] = v;
            }
        }
    } else {
        int idx = (bid - 1) * 256 + tid;
        const float* W; unsigned *H, *L; int BN, off;
        if (idx < 8192)       { W = W1o; H = h1o; L = l1o; BN = 128; off = idx; }
        else if (idx < 16384) { W = W1s; H = h1s; L = l1s; BN = 128; off = idx - 8192; }
        else if (idx < 20480) { W = W2o; H = h2o; L = l2o; BN = 64;  off = idx - 16384; }
        else                  { W = W2s; H = h2s; L = l2s; BN = 64;  off = idx - 20480; }
        int k2 = off / BN, n = off % BN;
        unsigned h, l;
        bsplit2(W[(2 * k2) * BN + n], W[(2 * k2 + 1) * BN + n], h, l);
        H[off] = h; L[off] = l;
    }
}

// ---------------- CSR: hist / scans / scatter ----------------
__global__ void k_hist2(const int* __restrict__ o_dst, const int* __restrict__ s_dst,
                        int* __restrict__ cntO, int* __restrict__ cntS, int E) {
    int i = blockIdx.x * blockDim.x + threadIdx.x;
    if (i < E) {
        atomicAdd(&cntO[o_dst[i]], 1);
        atomicAdd(&cntS[s_dst[i]], 1);
    }
}

__global__ void k_scan1(int* __restrict__ rp_base, int* __restrict__ bsum,
                        int n, int stride) {
    __shared__ int s[256];
    int* arr = rp_base + blockIdx.y * stride;
    int t = threadIdx.x;
    int base = blockIdx.x * 1024;
    int v[4]; int sum = 0;
#pragma unroll
    for (int j = 0; j < 4; ++j) {
        int i = base + t * 4 + j;
        v[j] = (i < n) ? arr[i] : 0;
        sum += v[j];
    }
    s[t] = sum; __syncthreads();
    for (int off = 1; off < 256; off <<= 1) {
        int x = (t >= off) ? s[t - off] : 0;
        __syncthreads();
        s[t] += x;
        __syncthreads();
    }
    int run = s[t] - sum;
    if (t == 255) bsum[blockIdx.y * 128 + blockIdx.x] = s[255];
#pragma unroll
    for (int j = 0; j < 4; ++j) {
        int i = base + t * 4 + j;
        if (i < n) arr[i] = run;
        run += v[j];
    }
}

__global__ void k_scan23(int* __restrict__ rp_base, const int* __restrict__ bsum,
                         int* __restrict__ cur_base, int n, int E, int stride) {
    int y = blockIdx.y;
    int* rp  = rp_base + y * stride;
    int* cur = cur_base + y * n;
    __shared__ int s_off;
    int i0 = blockIdx.x * blockDim.x;
    int chunk = i0 >> 10;
    if (threadIdx.x == 0) {
        int acc = 0;
        const int* bs = bsum + y * 128;
        for (int j = 0; j < chunk; ++j) acc += bs[j];
        s_off = acc;
    }
    __syncthreads();
    int i = i0 + threadIdx.x;
    if (i < n) {
        int v = rp[i] + s_off;
        rp[i] = v;
        cur[i] = v;
    } else if (i == n) {
        rp[n] = E;
    }
}

__global__ void k_scatter2(const int* __restrict__ o_dst, const int* __restrict__ o_src,
                           const float* __restrict__ o_val,
                           const int* __restrict__ s_dst, const int* __restrict__ s_src,
                           const float* __restrict__ s_val,
                           int* __restrict__ curO, int* __restrict__ curS,
                           int2* __restrict__ epO, int2* __restrict__ epS, int E) {
    int e = blockIdx.x * blockDim.x + threadIdx.x;
    if (e < E) {
        int d = o_dst[e];
        int p = atomicAdd(&curO[d], 1);
        epO[p] = make_int2(o_src[e], __float_as_int(o_val[e]));
        d = s_dst[e];
        p = atomicAdd(&curS[d], 1);
        epS[p] = make_int2(s_src[e], __float_as_int(s_val[e]));
    }
}

// ---------------- gate + pair output ----------------
__global__ void k_gate3(const float4* __restrict__ aggO, const float4* __restrict__ aggS,
                        const float* __restrict__ wc, float* __restrict__ ga,
                        float* __restrict__ gb, int N) {
    int n = blockIdx.x * blockDim.x + threadIdx.x;
    if (n >= N) return;
    float4 aO = aggO[n], aS = aggS[n];
    float g1  = aO.x + wc[129];
    float xl1 = aO.y + wc[130];
    float xh1 = aO.z + wc[131];
    float g2  = aS.x + wc[132];
    float xl2 = aS.y + wc[133];
    float xh2 = aS.z + wc[134];
    ga[n] = g1 * xl1 + g2 * xl2;
    gb[n] = g1 * xh1 + g2 * xh2;
}

__global__ void k_final(const void* __restrict__ idxv, const float* __restrict__ ga,
                        const float* __restrict__ gb, const float* __restrict__ wc,
                        float* __restrict__ out, int P, int N) {
    int p = blockIdx.x * blockDim.x + threadIdx.x;
    if (p >= P) return;
    long long i0, i1;
    if (g_i64flag) {
        const long long* qq = (const long long*)idxv;
        i0 = qq[p]; i1 = qq[(size_t)P + p];
    } else {
        const int* qq = (const int*)idxv;
        i0 = qq[p]; i1 = qq[(size_t)P + p];
    }
    i0 = i0 < 0 ? 0 : (i0 >= N ? N - 1 : i0);
    i1 = i1 < 0 ? 0 : (i1 >= N ? N - 1 : i1);
    out[p] = ga[i0] + gb[i1] + wc[128];
}

// ---------------- host ----------------
extern "C" void kernel_launch(void* const* d_in, const int* in_sizes, int n_in,
                              void* d_out, int out_size) {
    const float* x       = (const float*)d_in[0];
    const int*   o_edges = (const int*)d_in[1];
    const float* o_vals  = (const float*)d_in[2];
    const int*   s_edges = (const int*)d_in[3];
    const float* s_vals  = (const float*)d_in[4];
    const void*  idx     = d_in[5];
    const float* W_o1 = (const float*)d_in[6];
    const float* b_o1 = (const float*)d_in[7];
    const float* W_o2 = (const float*)d_in[8];
    const float* b_o2 = (const float*)d_in[9];
    const float* W_s1 = (const float*)d_in[10];
    const float* b_s1 = (const float*)d_in[11];
    const float* W_s2 = (const float*)d_in[12];
    const float* b_s2 = (const float*)d_in[13];
    const float* ag1  = (const float*)d_in[14];
    const float* ag2  = (const float*)d_in[15];
    const float* d1W  = (const float*)d_in[16];
    const float* d1b  = (const float*)d_in[17];
    const float* d2W  = (const float*)d_in[18];
    const float* d2b  = (const float*)d_in[19];
    float* out = (float*)d_out;

    const int N = in_sizes[0] / 128;
    const int E = in_sizes[2];
    const int P = in_sizes[5] / 2;

    float *s1o, *s1s, *ga, *gb, *wc;
    short *q1o, *q1s;
    unsigned *hoh, *hol, *hsh, *hsl;
    float4 *tO, *tS, *aggO, *aggS;
    int *rp, *cur, *bsum;
    int2 *ep;
    unsigned *h1o, *l1o, *h1s, *l1s, *h2o, *l2o, *h2s, *l2s;
    cudaGetSymbolAddress((void**)&hoh,  g_hoh);
    cudaGetSymbolAddress((void**)&hol,  g_hol);
    cudaGetSymbolAddress((void**)&hsh,  g_hsh);
    cudaGetSymbolAddress((void**)&hsl,  g_hsl);
    cudaGetSymbolAddress((void**)&q1o,  g_q1o);
    cudaGetSymbolAddress((void**)&q1s,  g_q1s);
    cudaGetSymbolAddress((void**)&s1o,  g_s1o);
    cudaGetSymbolAddress((void**)&s1s,  g_s1s);
    cudaGetSymbolAddress((void**)&tO,   g_tO);
    cudaGetSymbolAddress((void**)&tS,   g_tS);
    cudaGetSymbolAddress((void**)&aggO, g_aggO);
    cudaGetSymbolAddress((void**)&aggS, g_aggS);
    cudaGetSymbolAddress((void**)&ga,   g_av);
    cudaGetSymbolAddress((void**)&gb,   g_bv);
    cudaGetSymbolAddress((void**)&wc,   g_wc);
    cudaGetSymbolAddress((void**)&rp,   g_rp);
    cudaGetSymbolAddress((void**)&ep,   g_ep);
    cudaGetSymbolAddress((void**)&cur,  g_cur);
    cudaGetSymbolAddress((void**)&bsum, g_bsum);
    cudaGetSymbolAddress((void**)&h1o,  g_Wh1o);
    cudaGetSymbolAddress((void**)&l1o,  g_Wl1o);
    cudaGetSymbolAddress((void**)&h1s,  g_Wh1s);
    cudaGetSymbolAddress((void**)&l1s,  g_Wl1s);
    cudaGetSymbolAddress((void**)&h2o,  g_Wh2o);
    cudaGetSymbolAddress((void**)&l2o,  g_Wl2o);
    cudaGetSymbolAddress((void**)&h2s,  g_Wh2s);
    cudaGetSymbolAddress((void**)&l2s,  g_Wl2s);

    int* rpO = rp;
    int* rpS = rp + (N + 1);
    int* curO = cur;
    int* curS = cur + N;
    int2* epO = ep;
    int2* epS = ep + E;

    const int nb   = (N + 1023) / 1024;
    const int GB   = (N + 127) / 128;
    const int SB   = (E + 255) / 256;
    const int SPB  = (N + 7) / 8;
    const int S3B  = (N + 31) / 32;
    const int rp_n = 2 * (N + 1);

    const int SM128 = 3 * 128 * 20 * 4 + 2 * 3 * 8 * 136 * 4 + 512;
    const int SMDOT = 2 * 3 * 128 * 12 * 4 + 2 * 3 * 8 * 72 * 4 + 2048;
    cudaFuncSetAttribute(k_gemm_q128, cudaFuncAttributeMaxDynamicSharedMemorySize, SM128);
    cudaFuncSetAttribute(k_gemm_dot,  cudaFuncAttributeMaxDynamicSharedMemorySize, SMDOT);

    const bool conc = g_sr.ok;
    cudaStream_t sB = conc ? g_sr.sB : 0;

    int nwords = in_sizes[5];
    int probe = nwords < 256 ? nwords : 256;

    // first op on the capture stream; fork sB from it
    cudaMemsetAsync(rp, 0, (size_t)rp_n * sizeof(int), 0);
    if (conc) {
        cudaEventRecord(g_sr.evFork, 0);
        cudaStreamWaitEvent(sB, g_sr.evFork, 0);
    }

    // sB: prep + gemm_o (release early) + gemm_s
    k_prep<<<97, 256, 0, sB>>>((const int*)idx, probe, d1W, d1b, d2W, d2b,
                               b_o2, b_s2, ag1, ag2, wc,
                               W_o1, W_s1, W_o2, W_s2,
                               h1o, l1o, h1s, l1s, h2o, l2o, h2s, l2s);
    k_gemm_q128<<<GB, 256, SM128, sB>>>(x, h1o, l1o, q1o, s1o, N);
    if (conc) cudaEventRecord(g_sr.evG1, sB);        // q1o ready
    k_gemm_q128<<<GB, 256, SM128, sB>>>(x, h1s, l1s, q1s, s1s, N);

    // stream0: CSR chain (concurrent with sB)
    k_hist2<<<SB, 256>>>(o_edges, s_edges, rpO, rpS, E);
    { dim3 g(nb, 2); k_scan1<<<g, 256>>>(rp, bsum, N, N + 1); }
    { dim3 g((N + 1 + 255) / 256, 2); k_scan23<<<g, 256>>>(rp, bsum, cur, N, E, N + 1); }
    k_scatter2<<<SB, 256>>>(o_edges, o_edges + E, o_vals,
                            s_edges, s_edges + E, s_vals,
                            curO, curS, epO, epS, E);
    if (conc) {
        cudaEventRecord(g_sr.evCSR, 0);
        cudaStreamWaitEvent(0, g_sr.evG1, 0);   // s0 phase-3 needs q1o
        cudaStreamWaitEvent(sB, g_sr.evCSR, 0); // sB phase-3 needs CSR
    }

    // branch o on stream0, branch s on sB
    k_spmm128<<<SPB, 256>>>(rpO, epO, q1o, s1o, b_o1, hoh, hol, N);
    k_gemm_dot<<<GB, 256, SMDOT>>>(hoh, hol, h2o, l2o, ag1, tO, wc, N);
    k_spmm3<<<S3B, 256>>>(rpO, epO, tO, aggO, N);
    k_spmm128<<<SPB, 256, 0, sB>>>(rpS, epS, q1s, s1s, b_s1, hsh, hsl, N);
    k_gemm_dot<<<GB, 256, SMDOT, sB>>>(hsh, hsl, h2s, l2s, ag2, tS, wc, N);
    k_spmm3<<<S3B, 256, 0, sB>>>(rpS, epS, tS, aggS, N);
    if (conc) {
        cudaEventRecord(g_sr.evS, sB);
        cudaStreamWaitEvent(0, g_sr.evS, 0);
    }

    // tail
    k_gate3<<<(N + 255) / 256, 256>>>(aggO, aggS, wc, ga, gb, N);
    k_final<<<(P + 255) / 256, 256>>>(idx, ga, gb, wc, out, P, N);
}

// round 17
// speedup vs baseline: 1.2221x; 1.1423x over previous
#include <cuda_runtime.h>
#include <cuda_bf16.h>

#define NMAX 100000
#define EMAX 1600000

// ---------------- scratch ----------------
static __device__ __align__(16) short  g_q1o [ (size_t)NMAX*128 ];
static __device__ __align__(16) short  g_q1s [ (size_t)NMAX*128 ];
static __device__ __align__(16) float  g_s1o [ NMAX ];
static __device__ __align__(16) float  g_s1s [ NMAX ];
static __device__ __align__(16) float4 g_tO  [ NMAX ];
static __device__ __align__(16) float4 g_tS  [ NMAX ];
static __device__ __align__(16) float4 g_aggO[ NMAX ];
static __device__ __align__(16) float4 g_aggS[ NMAX ];
static __device__ __align__(16) float  g_av  [ NMAX ];
static __device__ __align__(16) float  g_bv  [ NMAX ];
static __device__ __align__(16) float  g_wc  [ 144 ];   // w[0..127], c@128, dots@129..134
static __device__ __align__(16) float  g_uO  [ 3*128 ]; // u vectors: W_o2 @ {ag1, w_lo, w_hi}
static __device__ __align__(16) float  g_uS  [ 3*128 ];
static __device__ __align__(16) int    g_rp  [ 2*(NMAX+1) ];
static __device__ __align__(16) int2   g_ep  [ (size_t)2*EMAX ];
static __device__ __align__(16) int    g_cur [ 2*NMAX ];
static __device__ __align__(16) int    g_bsum[ 256 ];
static __device__ __align__(16) unsigned g_Wh1o[64*128], g_Wl1o[64*128];
static __device__ __align__(16) unsigned g_Wh1s[64*128], g_Wl1s[64*128];
static __device__            int   g_i64flag;

// ---------------- stream/event resources (static init) ----------------
struct StreamRes {
    cudaStream_t sB;
    cudaEvent_t evFork, evG1, evCSR, evS;
    bool ok;
    StreamRes() : sB(0), evFork(0), evG1(0), evCSR(0), evS(0), ok(false) {
        if (cudaStreamCreate(&sB) != cudaSuccess) { sB = 0; return; }
        if (cudaEventCreateWithFlags(&evFork, cudaEventDisableTiming) != cudaSuccess) return;
        if (cudaEventCreateWithFlags(&evG1,   cudaEventDisableTiming) != cudaSuccess) return;
        if (cudaEventCreateWithFlags(&evCSR,  cudaEventDisableTiming) != cudaSuccess) return;
        if (cudaEventCreateWithFlags(&evS,    cudaEventDisableTiming) != cudaSuccess) return;
        ok = true;
    }
};
static StreamRes g_sr;

// ---------------- bf16 hi/lo split ----------------
__device__ __forceinline__ void bsplit2(float x0, float x1, unsigned& h, unsigned& l) {
    unsigned hp;
    asm("cvt.rn.bf16x2.f32 %0, %1, %2;" : "=r"(hp) : "f"(x1), "f"(x0));
    float fh0 = __uint_as_float(hp << 16);
    float fh1 = __uint_as_float(hp & 0xFFFF0000u);
    float r0 = x0 - fh0, r1 = x1 - fh1;
    asm("cvt.rn.bf16x2.f32 %0, %1, %2;" : "=r"(l) : "f"(r1), "f"(r0));
    h = hp;
}

#define MMA_BF16(acc, a, b0, b1)                                              \
    asm volatile(                                                             \
        "mma.sync.aligned.m16n8k16.row.col.f32.bf16.bf16.f32 "                \
        "{%0,%1,%2,%3}, {%4,%5,%6,%7}, {%8,%9}, {%0,%1,%2,%3};\n"             \
        : "+f"(acc[0]), "+f"(acc[1]), "+f"(acc[2]), "+f"(acc[3])              \
        : "r"(a[0]), "r"(a[1]), "r"(a[2]), "r"(a[3]), "r"(b0), "r"(b1))

// ---------------- GEMM-128 (fp32 A, in-kernel split) + int16 rowquant ----------------
__global__ __launch_bounds__(256, 2)
void k_gemm_q128(const float* __restrict__ A,
                 const unsigned* __restrict__ Bh, const unsigned* __restrict__ Bl,
                 short* __restrict__ q, float* __restrict__ sc, int M) {
    constexpr int BM = 128, BK = 16, KTOT = 128, NCH = KTOT / BK, NST = 3;
    constexpr int BN = 128, WN = 64, NT = 8;
    constexpr int SAW = BK + 4, SBW = BN + 8;
    extern __shared__ char dynsmem[];
    float*    sA   = (float*)dynsmem;
    unsigned* sBh  = (unsigned*)(dynsmem + NST * BM * SAW * 4);
    unsigned* sBl  = sBh + NST * 8 * SBW;
    int*      rmax = (int*)(sBl + NST * 8 * SBW);

    const int tid  = threadIdx.x;
    const int wid  = tid >> 5, lane = tid & 31;
    const int wm   = wid & 3,  wn   = wid >> 2;
    const int g    = lane >> 2, tig = lane & 3;
    const int row0 = blockIdx.x * BM;

    if (tid < BM) rmax[tid] = 0;

    float acc[2][NT][4];
#pragma unroll
    for (int mt = 0; mt < 2; ++mt)
#pragma unroll
        for (int nt = 0; nt < NT; ++nt)
#pragma unroll
            for (int i = 0; i < 4; ++i) acc[mt][nt][i] = 0.f;

    auto loadA = [&](int ck, int st) {
#pragma unroll
        for (int i = 0; i < 2; ++i) {
            int idx = i * 256 + tid;
            int r = idx >> 2, c4 = idx & 3;
            const float* gp = A + (size_t)(row0 + r) * KTOT + ck * BK + c4 * 4;
            unsigned sp = (unsigned)__cvta_generic_to_shared(&sA[(st * BM + r) * SAW + c4 * 4]);
            int bytes = (row0 + r < M) ? 16 : 0;
            asm volatile("cp.async.cg.shared.global [%0], [%1], 16, %2;\n"
                         :: "r"(sp), "l"(gp), "r"(bytes));
        }
    };
    auto loadB = [&](int ck, int st) {
        int r = tid >> 5, c4 = tid & 31;
        const unsigned* gh = Bh + (size_t)(ck * 8 + r) * BN + c4 * 4;
        const unsigned* gl = Bl + (size_t)(ck * 8 + r) * BN + c4 * 4;
        unsigned sph = (unsigned)__cvta_generic_to_shared(&sBh[(st * 8 + r) * SBW + c4 * 4]);
        unsigned spl = (unsigned)__cvta_generic_to_shared(&sBl[(st * 8 + r) * SBW + c4 * 4]);
        asm volatile("cp.async.cg.shared.global [%0], [%1], 16, 16;\n" :: "r"(sph), "l"(gh));
        asm volatile("cp.async.cg.shared.global [%0], [%1], 16, 16;\n" :: "r"(spl), "l"(gl));
    };
    auto compute = [&](int st) {
        unsigned ah[2][4], al[2][4];
#pragma unroll
        for (int mt = 0; mt < 2; ++mt) {
            int r = wm * 32 + mt * 16 + g;
            float2 p0 = *(const float2*)&sA[(st * BM + r    ) * SAW + 2 * tig];
            float2 p1 = *(const float2*)&sA[(st * BM + r + 8) * SAW + 2 * tig];
            float2 p2 = *(const float2*)&sA[(st * BM + r    ) * SAW + 2 * tig + 8];
            float2 p3 = *(const float2*)&sA[(st * BM + r + 8) * SAW + 2 * tig + 8];
            bsplit2(p0.x, p0.y, ah[mt][0], al[mt][0]);
            bsplit2(p1.x, p1.y, ah[mt][1], al[mt][1]);
            bsplit2(p2.x, p2.y, ah[mt][2], al[mt][2]);
            bsplit2(p3.x, p3.y, ah[mt][3], al[mt][3]);
        }
#pragma unroll
        for (int nt = 0; nt < NT; ++nt) {
            int c = wn * WN + nt * 8 + g;
            unsigned b0h = sBh[(st * 8 + tig    ) * SBW + c];
            unsigned b1h = sBh[(st * 8 + tig + 4) * SBW + c];
            unsigned b0l = sBl[(st * 8 + tig    ) * SBW + c];
            unsigned b1l = sBl[(st * 8 + tig + 4) * SBW + c];
#pragma unroll
            for (int mt = 0; mt < 2; ++mt) {
                MMA_BF16(acc[mt][nt], ah[mt], b0h, b1h);
                MMA_BF16(acc[mt][nt], al[mt], b0h, b1h);
                MMA_BF16(acc[mt][nt], ah[mt], b0l, b1l);
            }
        }
    };

    loadA(0, 0); loadB(0, 0);
    asm volatile("cp.async.commit_group;\n");
    loadA(1, 1); loadB(1, 1);
    asm volatile("cp.async.commit_group;\n");
#pragma unroll
    for (int ck = 0; ck < NCH; ++ck) {
        if (ck + 1 < NCH) asm volatile("cp.async.wait_group 1;\n");
        else              asm volatile("cp.async.wait_group 0;\n");
        __syncthreads();
        if (ck + 2 < NCH) {
            loadA(ck + 2, (ck + 2) % 3); loadB(ck + 2, (ck + 2) % 3);
            asm volatile("cp.async.commit_group;\n");
        }
        compute(ck % 3);
    }

#pragma unroll
    for (int mt = 0; mt < 2; ++mt) {
        float m0 = 0.f, m1 = 0.f;
#pragma unroll
        for (int nt = 0; nt < NT; ++nt) {
            m0 = fmaxf(m0, fmaxf(fabsf(acc[mt][nt][0]), fabsf(acc[mt][nt][1])));
            m1 = fmaxf(m1, fmaxf(fabsf(acc[mt][nt][2]), fabsf(acc[mt][nt][3])));
        }
        m0 = fmaxf(m0, __shfl_xor_sync(0xFFFFFFFFu, m0, 1));
        m0 = fmaxf(m0, __shfl_xor_sync(0xFFFFFFFFu, m0, 2));
        m1 = fmaxf(m1, __shfl_xor_sync(0xFFFFFFFFu, m1, 1));
        m1 = fmaxf(m1, __shfl_xor_sync(0xFFFFFFFFu, m1, 2));
        if (tig == 0) {
            atomicMax(&rmax[wm * 32 + mt * 16 + g],     __float_as_int(m0));
            atomicMax(&rmax[wm * 32 + mt * 16 + g + 8], __float_as_int(m1));
        }
    }
    __syncthreads();
#pragma unroll
    for (int mt = 0; mt < 2; ++mt) {
        int lr0 = wm * 32 + mt * 16 + g;
        float mx0 = __int_as_float(rmax[lr0]);
        float mx1 = __int_as_float(rmax[lr0 + 8]);
        float si0 = (mx0 > 0.f) ? (32766.f / mx0) : 0.f;
        float si1 = (mx1 > 0.f) ? (32766.f / mx1) : 0.f;
        int gr0 = row0 + lr0, gr1 = gr0 + 8;
        if (wn == 0 && tig == 0) {
            if (gr0 < M) sc[gr0] = (mx0 > 0.f) ? (mx0 / 32766.f) : 0.f;
            if (gr1 < M) sc[gr1] = (mx1 > 0.f) ? (mx1 / 32766.f) : 0.f;
        }
#pragma unroll
        for (int nt = 0; nt < NT; ++nt) {
            int c = wn * 64 + nt * 8 + tig * 2;
            if (gr0 < M) {
                int a = __float2int_rn(acc[mt][nt][0] * si0);
                int b = __float2int_rn(acc[mt][nt][1] * si0);
                *(unsigned*)(q + (size_t)gr0 * BN + c) = (a & 0xFFFF) | (b << 16);
            }
            if (gr1 < M) {
                int a = __float2int_rn(acc[mt][nt][2] * si1);
                int b = __float2int_rn(acc[mt][nt][3] * si1);
                *(unsigned*)(q + (size_t)gr1 * BN + c) = (a & 0xFFFF) | (b << 16);
            }
        }
    }
}

// ---------------- SpMM-128 + fused relu + 3-vector projection ----------------
// t[w] = (relu(agg+bias)·u0, ·u1, ·u2); u = [3][128] floats.
__global__ void k_spmm128t(const int* __restrict__ rp, const int2* __restrict__ ep,
                           const short* __restrict__ q, const float* __restrict__ sc,
                           const float* __restrict__ bias, const float* __restrict__ u,
                           float4* __restrict__ t, int M) {
    int w = blockIdx.x * 8 + (threadIdx.x >> 5);
    if (w >= M) return;
    int l = threadIdx.x & 31;
    float4 acc = *(const float4*)(bias + l * 4);
    int p = rp[w], e = rp[w + 1];
    for (; p + 7 < e; p += 8) {
        int2 ee[8];
#pragma unroll
        for (int j = 0; j < 8; ++j) ee[j] = __ldg(&ep[p + j]);
        float cc[8];
#pragma unroll
        for (int j = 0; j < 8; ++j) cc[j] = __int_as_float(ee[j].y) * __ldg(&sc[ee[j].x]);
        int2 dd[8];
#pragma unroll
        for (int j = 0; j < 8; ++j) dd[j] = *(const int2*)(q + (size_t)ee[j].x * 128 + l * 4);
#pragma unroll
        for (int j = 0; j < 8; ++j) {
            acc.x = fmaf(cc[j], (float)((short)(dd[j].x)),       acc.x);
            acc.y = fmaf(cc[j], (float)((short)(dd[j].x >> 16)), acc.y);
            acc.z = fmaf(cc[j], (float)((short)(dd[j].y)),       acc.z);
            acc.w = fmaf(cc[j], (float)((short)(dd[j].y >> 16)), acc.w);
        }
    }
    for (; p < e; ++p) {
        int2 e0 = __ldg(&ep[p]);
        float c0 = __int_as_float(e0.y) * __ldg(&sc[e0.x]);
        int2 d0 = *(const int2*)(q + (size_t)e0.x * 128 + l * 4);
        acc.x = fmaf(c0, (float)((short)(d0.x)),       acc.x);
        acc.y = fmaf(c0, (float)((short)(d0.x >> 16)), acc.y);
        acc.z = fmaf(c0, (float)((short)(d0.y)),       acc.z);
        acc.w = fmaf(c0, (float)((short)(d0.y >> 16)), acc.w);
    }
    acc.x = fmaxf(acc.x, 0.f); acc.y = fmaxf(acc.y, 0.f);
    acc.z = fmaxf(acc.z, 0.f); acc.w = fmaxf(acc.w, 0.f);
    // projection epilogue: lane l holds cols 4l..4l+3
    float4 u0 = __ldg((const float4*)(u)       + l);
    float4 u1 = __ldg((const float4*)(u + 128) + l);
    float4 u2 = __ldg((const float4*)(u + 256) + l);
    float p0 = acc.x * u0.x + acc.y * u0.y + acc.z * u0.z + acc.w * u0.w;
    float p1 = acc.x * u1.x + acc.y * u1.y + acc.z * u1.z + acc.w * u1.w;
    float p2 = acc.x * u2.x + acc.y * u2.y + acc.z * u2.z + acc.w * u2.w;
#pragma unroll
    for (int o = 16; o > 0; o >>= 1) {
        p0 += __shfl_xor_sync(0xFFFFFFFFu, p0, o);
        p1 += __shfl_xor_sync(0xFFFFFFFFu, p1, o);
        p2 += __shfl_xor_sync(0xFFFFFFFFu, p2, o);
    }
    if (l == 0) t[w] = make_float4(p0, p1, p2, 0.f);
}

// ---------------- SpMM-3 ----------------
__global__ void k_spmm3(const int* __restrict__ rp, const int2* __restrict__ ep,
                        const float4* __restrict__ t, float4* __restrict__ agg, int M) {
    int node = blockIdx.x * 32 + (threadIdx.x >> 3);
    int l = threadIdx.x & 7;
    bool valid = node < M;
    int p = valid ? rp[node] : 0;
    int e = valid ? rp[node + 1] : 0;
    float ax = 0.f, ay = 0.f, az = 0.f;
    for (p += l; p < e; p += 8) {
        int2 e0 = __ldg(&ep[p]);
        float c = __int_as_float(e0.y);
        float4 tv = __ldg(&t[e0.x]);
        ax = fmaf(c, tv.x, ax);
        ay = fmaf(c, tv.y, ay);
        az = fmaf(c, tv.z, az);
    }
#pragma unroll
    for (int o = 4; o > 0; o >>= 1) {
        ax += __shfl_xor_sync(0xFFFFFFFFu, ax, o, 8);
        ay += __shfl_xor_sync(0xFFFFFFFFu, ay, o, 8);
        az += __shfl_xor_sync(0xFFFFFFFFu, az, o, 8);
    }
    if (valid && l == 0) agg[node] = make_float4(ax, ay, az, 0.f);
}

// ---------------- prep: detect + wc + bias dots + pack W1 ----------------
__global__ void k_prep(const int* __restrict__ idx32, int nwords,
                       const float* __restrict__ d1W, const float* __restrict__ d1b,
                       const float* __restrict__ d2W, const float* __restrict__ d2b,
                       const float* __restrict__ b_o2, const float* __restrict__ b_s2,
                       const float* __restrict__ ag1, const float* __restrict__ ag2,
                       float* __restrict__ wc,
                       const float* __restrict__ W1o, const float* __restrict__ W1s,
                       unsigned* __restrict__ h1o, unsigned* __restrict__ l1o,
                       unsigned* __restrict__ h1s, unsigned* __restrict__ l1s) {
    int bid = blockIdx.x, tid = threadIdx.x;
    if (bid == 0) {
        if (tid < 128) {
            float s = 0.f;
#pragma unroll 8
            for (int j = 0; j < 64; ++j) s = fmaf(d1W[tid * 64 + j], d2W[j], s);
            wc[tid] = s;
            if (tid == 0) {
                float c = d2b[0];
                for (int j = 0; j < 64; ++j) c = fmaf(d1b[j], d2W[j], c);
                wc[128] = c;
            }
        } else if (tid < 160) {
            int t = tid - 128;
            int bad = 0;
#pragma unroll
            for (int j = 0; j < 4; ++j) {
                int w = (t * 4 + j) * 2 + 1;
                if (w < nwords && idx32[w] != 0) bad = 1;
            }
            unsigned m = __ballot_sync(0xFFFFFFFFu, bad);
            if (t == 0) g_i64flag = (m == 0u) ? 1 : 0;
        }
        __syncthreads();
        if ((tid >> 5) == 6) {
            int lane = tid & 31;
            for (int d = 0; d < 6; ++d) {
                const float* A = (d < 3) ? b_o2 : b_s2;
                const float* B = (d == 0) ? ag1 : (d == 3) ? ag2
                               : ((d % 3) == 1) ? wc : wc + 64;
                float v = A[lane] * B[lane] + A[lane + 32] * B[lane + 32];
#pragma unroll
                for (int o = 16; o > 0; o >>= 1)
                    v += __shfl_xor_sync(0xFFFFFFFFu, v, o);
                if (lane == 0) wc[129 + d] = v;
            }
        }
    } else {
        int idx = (bid - 1) * 256 + tid;   // 0..16383
        const float* W; unsigned *H, *L; int off;
        if (idx < 8192) { W = W1o; H = h1o; L = l1o; off = idx; }
        else            { W = W1s; H = h1s; L = l1s; off = idx - 8192; }
        int k2 = off / 128, n = off % 128;
        unsigned h, l;
        bsplit2(W[(2 * k2) * 128 + n], W[(2 * k2 + 1) * 128 + n], h, l);
        H[off] = h; L[off] = l;
    }
}

// ---------------- prepu: u = W2 @ {ag, w_lo, w_hi} per branch (needs wc) ----------------
__global__ void k_prepu(const float* __restrict__ W_o2, const float* __restrict__ W_s2,
                        const float* __restrict__ ag1, const float* __restrict__ ag2,
                        const float* __restrict__ wc,
                        float* __restrict__ uO, float* __restrict__ uS) {
    int e = blockIdx.x * 256 + threadIdx.x;   // 0..767
    if (e >= 768) return;
    int j = e >> 7;          // 0..5
    int c = e & 127;
    int branch = j / 3;      // 0: o, 1: s
    int vsel = j % 3;        // 0: ag, 1: w_lo, 2: w_hi
    const float* W = branch ? W_s2 : W_o2;
    const float* v = (vsel == 0) ? (branch ? ag2 : ag1)
                   : (vsel == 1) ? wc : wc + 64;
    float s = 0.f;
#pragma unroll 8
    for (int k = 0; k < 64; ++k) s = fmaf(W[c * 64 + k], v[k], s);
    (branch ? uS : uO)[vsel * 128 + c] = s;
}

// ---------------- CSR: hist / scans / scatter ----------------
__global__ void k_hist2(const int* __restrict__ o_dst, const int* __restrict__ s_dst,
                        int* __restrict__ cntO, int* __restrict__ cntS, int E) {
    int i = blockIdx.x * blockDim.x + threadIdx.x;
    if (i < E) {
        atomicAdd(&cntO[o_dst[i]], 1);
        atomicAdd(&cntS[s_dst[i]], 1);
    }
}

__global__ void k_scan1(int* __restrict__ rp_base, int* __restrict__ bsum,
                        int n, int stride) {
    __shared__ int s[256];
    int* arr = rp_base + blockIdx.y * stride;
    int t = threadIdx.x;
    int base = blockIdx.x * 1024;
    int v[4]; int sum = 0;
#pragma unroll
    for (int j = 0; j < 4; ++j) {
        int i = base + t * 4 + j;
        v[j] = (i < n) ? arr[i] : 0;
        sum += v[j];
    }
    s[t] = sum; __syncthreads();
    for (int off = 1; off < 256; off <<= 1) {
        int x = (t >= off) ? s[t - off] : 0;
        __syncthreads();
        s[t] += x;
        __syncthreads();
    }
    int run = s[t] - sum;
    if (t == 255) bsum[blockIdx.y * 128 + blockIdx.x] = s[255];
#pragma unroll
    for (int j = 0; j < 4; ++j) {
        int i = base + t * 4 + j;
        if (i < n) arr[i] = run;
        run += v[j];
    }
}

__global__ void k_scan23(int* __restrict__ rp_base, const int* __restrict__ bsum,
                         int* __restrict__ cur_base, int n, int E, int stride) {
    int y = blockIdx.y;
    int* rp  = rp_base + y * stride;
    int* cur = cur_base + y * n;
    __shared__ int s_off;
    int i0 = blockIdx.x * blockDim.x;
    int chunk = i0 >> 10;
    if (threadIdx.x == 0) {
        int acc = 0;
        const int* bs = bsum + y * 128;
        for (int j = 0; j < chunk; ++j) acc += bs[j];
        s_off = acc;
    }
    __syncthreads();
    int i = i0 + threadIdx.x;
    if (i < n) {
        int v = rp[i] + s_off;
        rp[i] = v;
        cur[i] = v;
    } else if (i == n) {
        rp[n] = E;
    }
}

__global__ void k_scatter2(const int* __restrict__ o_dst, const int* __restrict__ o_src,
                           const float* __restrict__ o_val,
                           const int* __restrict__ s_dst, const int* __restrict__ s_src,
                           const float* __restrict__ s_val,
                           int* __restrict__ curO, int* __restrict__ curS,
                           int2* __restrict__ epO, int2* __restrict__ epS, int E) {
    int e = blockIdx.x * blockDim.x + threadIdx.x;
    if (e < E) {
        int d = o_dst[e];
        int p = atomicAdd(&curO[d], 1);
        epO[p] = make_int2(o_src[e], __float_as_int(o_val[e]));
        d = s_dst[e];
        p = atomicAdd(&curS[d], 1);
        epS[p] = make_int2(s_src[e], __float_as_int(s_val[e]));
    }
}

// ---------------- gate + pair output ----------------
__global__ void k_gate3(const float4* __restrict__ aggO, const float4* __restrict__ aggS,
                        const float* __restrict__ wc, float* __restrict__ ga,
                        float* __restrict__ gb, int N) {
    int n = blockIdx.x * blockDim.x + threadIdx.x;
    if (n >= N) return;
    float4 aO = aggO[n], aS = aggS[n];
    float g1  = aO.x + wc[129];
    float xl1 = aO.y + wc[130];
    float xh1 = aO.z + wc[131];
    float g2  = aS.x + wc[132];
    float xl2 = aS.y + wc[133];
    float xh2 = aS.z + wc[134];
    ga[n] = g1 * xl1 + g2 * xl2;
    gb[n] = g1 * xh1 + g2 * xh2;
}

__global__ void k_final(const void* __restrict__ idxv, const float* __restrict__ ga,
                        const float* __restrict__ gb, const float* __restrict__ wc,
                        float* __restrict__ out, int P, int N) {
    int p = blockIdx.x * blockDim.x + threadIdx.x;
    if (p >= P) return;
    long long i0, i1;
    if (g_i64flag) {
        const long long* qq = (const long long*)idxv;
        i0 = qq[p]; i1 = qq[(size_t)P + p];
    } else {
        const int* qq = (const int*)idxv;
        i0 = qq[p]; i1 = qq[(size_t)P + p];
    }
    i0 = i0 < 0 ? 0 : (i0 >= N ? N - 1 : i0);
    i1 = i1 < 0 ? 0 : (i1 >= N ? N - 1 : i1);
    out[p] = ga[i0] + gb[i1] + wc[128];
}

// ---------------- host ----------------
extern "C" void kernel_launch(void* const* d_in, const int* in_sizes, int n_in,
                              void* d_out, int out_size) {
    const float* x       = (const float*)d_in[0];
    const int*   o_edges = (const int*)d_in[1];
    const float* o_vals  = (const float*)d_in[2];
    const int*   s_edges = (const int*)d_in[3];
    const float* s_vals  = (const float*)d_in[4];
    const void*  idx     = d_in[5];
    const float* W_o1 = (const float*)d_in[6];
    const float* b_o1 = (const float*)d_in[7];
    const float* W_o2 = (const float*)d_in[8];
    const float* b_o2 = (const float*)d_in[9];
    const float* W_s1 = (const float*)d_in[10];
    const float* b_s1 = (const float*)d_in[11];
    const float* W_s2 = (const float*)d_in[12];
    const float* b_s2 = (const float*)d_in[13];
    const float* ag1  = (const float*)d_in[14];
    const float* ag2  = (const float*)d_in[15];
    const float* d1W  = (const float*)d_in[16];
    const float* d1b  = (const float*)d_in[17];
    const float* d2W  = (const float*)d_in[18];
    const float* d2b  = (const float*)d_in[19];
    float* out = (float*)d_out;

    const int N = in_sizes[0] / 128;
    const int E = in_sizes[2];
    const int P = in_sizes[5] / 2;

    float *s1o, *s1s, *ga, *gb, *wc, *uO, *uS;
    short *q1o, *q1s;
    float4 *tO, *tS, *aggO, *aggS;
    int *rp, *cur, *bsum;
    int2 *ep;
    unsigned *h1o, *l1o, *h1s, *l1s;
    cudaGetSymbolAddress((void**)&q1o,  g_q1o);
    cudaGetSymbolAddress((void**)&q1s,  g_q1s);
    cudaGetSymbolAddress((void**)&s1o,  g_s1o);
    cudaGetSymbolAddress((void**)&s1s,  g_s1s);
    cudaGetSymbolAddress((void**)&tO,   g_tO);
    cudaGetSymbolAddress((void**)&tS,   g_tS);
    cudaGetSymbolAddress((void**)&aggO, g_aggO);
    cudaGetSymbolAddress((void**)&aggS, g_aggS);
    cudaGetSymbolAddress((void**)&ga,   g_av);
    cudaGetSymbolAddress((void**)&gb,   g_bv);
    cudaGetSymbolAddress((void**)&wc,   g_wc);
    cudaGetSymbolAddress((void**)&uO,   g_uO);
    cudaGetSymbolAddress((void**)&uS,   g_uS);
    cudaGetSymbolAddress((void**)&rp,   g_rp);
    cudaGetSymbolAddress((void**)&ep,   g_ep);
    cudaGetSymbolAddress((void**)&cur,  g_cur);
    cudaGetSymbolAddress((void**)&bsum, g_bsum);
    cudaGetSymbolAddress((void**)&h1o,  g_Wh1o);
    cudaGetSymbolAddress((void**)&l1o,  g_Wl1o);
    cudaGetSymbolAddress((void**)&h1s,  g_Wh1s);
    cudaGetSymbolAddress((void**)&l1s,  g_Wl1s);

    int* rpO = rp;
    int* rpS = rp + (N + 1);
    int* curO = cur;
    int* curS = cur + N;
    int2* epO = ep;
    int2* epS = ep + E;

    const int nb   = (N + 1023) / 1024;
    const int GB   = (N + 127) / 128;
    const int SB   = (E + 255) / 256;
    const int SPB  = (N + 7) / 8;
    const int S3B  = (N + 31) / 32;
    const int rp_n = 2 * (N + 1);

    const int SM128 = 3 * 128 * 20 * 4 + 2 * 3 * 8 * 136 * 4 + 512;
    cudaFuncSetAttribute(k_gemm_q128, cudaFuncAttributeMaxDynamicSharedMemorySize, SM128);

    const bool conc = g_sr.ok;
    cudaStream_t sB = conc ? g_sr.sB : 0;

    int nwords = in_sizes[5];
    int probe = nwords < 256 ? nwords : 256;

    // first op on the capture stream; fork sB from it
    cudaMemsetAsync(rp, 0, (size_t)rp_n * sizeof(int), 0);
    if (conc) {
        cudaEventRecord(g_sr.evFork, 0);
        cudaStreamWaitEvent(sB, g_sr.evFork, 0);
    }

    // sB: prep + prepu + gemm_o (release early) + gemm_s
    k_prep<<<65, 256, 0, sB>>>((const int*)idx, probe, d1W, d1b, d2W, d2b,
                               b_o2, b_s2, ag1, ag2, wc,
                               W_o1, W_s1, h1o, l1o, h1s, l1s);
    k_prepu<<<3, 256, 0, sB>>>(W_o2, W_s2, ag1, ag2, wc, uO, uS);
    k_gemm_q128<<<GB, 256, SM128, sB>>>(x, h1o, l1o, q1o, s1o, N);
    if (conc) cudaEventRecord(g_sr.evG1, sB);        // q1o + u ready
    k_gemm_q128<<<GB, 256, SM128, sB>>>(x, h1s, l1s, q1s, s1s, N);

    // stream0: CSR chain (concurrent with sB)
    k_hist2<<<SB, 256>>>(o_edges, s_edges, rpO, rpS, E);
    { dim3 g(nb, 2); k_scan1<<<g, 256>>>(rp, bsum, N, N + 1); }
    { dim3 g((N + 1 + 255) / 256, 2); k_scan23<<<g, 256>>>(rp, bsum, cur, N, E, N + 1); }
    k_scatter2<<<SB, 256>>>(o_edges, o_edges + E, o_vals,
                            s_edges, s_edges + E, s_vals,
                            curO, curS, epO, epS, E);
    if (conc) {
        cudaEventRecord(g_sr.evCSR, 0);
        cudaStreamWaitEvent(0, g_sr.evG1, 0);   // s0 phase-3 needs q1o + u
        cudaStreamWaitEvent(sB, g_sr.evCSR, 0); // sB phase-3 needs CSR
    }

    // branch o on stream0, branch s on sB
    k_spmm128t<<<SPB, 256>>>(rpO, epO, q1o, s1o, b_o1, uO, tO, N);
    k_spmm3<<<S3B, 256>>>(rpO, epO, tO, aggO, N);
    k_spmm128t<<<SPB, 256, 0, sB>>>(rpS, epS, q1s, s1s, b_s1, uS, tS, N);
    k_spmm3<<<S3B, 256, 0, sB>>>(rpS, epS, tS, aggS, N);
    if (conc) {
        cudaEventRecord(g_sr.evS, sB);
        cudaStreamWaitEvent(0, g_sr.evS, 0);
    }

    // tail
    k_gate3<<<(N + 255) / 256, 256>>>(aggO, aggS, wc, ga, gb, N);
    k_final<<<(P + 255) / 256, 256>>>(idx, ga, gb, wc, out, P, N);
}